// round 1
// baseline (speedup 1.0000x reference)
#include <cuda_runtime.h>

#define NN 50000
#define DD 128
#define EE 1600000
#define KATT 20

// ---------------- scratch (static device allocations) ----------------
__device__ float g_qkv[NN * 384];
__device__ float g_attn[NN * DD];
__device__ float g_a[NN * DD];
__device__ float g_tmp[NN * 512];
__device__ float g_h[NN * DD];
__device__ float g_h2[NN * DD];
__device__ float g_neigh[NN * DD];
__device__ int   g_deg[NN];
__device__ int   g_off[NN + 1];
__device__ int   g_cnt[NN];
__device__ int   g_csr[EE];

// ---------------- fused GEMM:  C = epi(A @ W^T + b) ----------------
// W is [OUT, IN] row-major. Block: 64 rows x 128 cols, 256 threads,
// each thread 8x4 outputs. Optional: RELU(acc+b), +residual, LayerNorm
// (only valid when OUT == 128, one y-block -> full row in block).
// SPLIT: logical A = concat(A, A2) along K (each stride 128).
template <int IN, int OUT, bool RELU, bool RES, bool LN, bool SPLIT>
__global__ __launch_bounds__(256) void gemm_fused(
    const float* __restrict__ A, const float* __restrict__ A2,
    const float* __restrict__ W, const float* __restrict__ bias,
    const float* __restrict__ res,
    const float* __restrict__ lng, const float* __restrict__ lnb,
    float* __restrict__ C, int nrows)
{
    __shared__ float As[16][64 + 1];   // transposed A tile [k][row]
    __shared__ float Ws[16][128];      // transposed W tile [k][col]

    const int tid  = threadIdx.x;
    const int trow = tid >> 5;         // 0..7  (warp id)
    const int tcol = tid & 31;         // 0..31
    const int row0 = blockIdx.x * 64;
    const int col0 = blockIdx.y * 128;

    float acc[8][4];
#pragma unroll
    for (int i = 0; i < 8; i++)
#pragma unroll
        for (int j = 0; j < 4; j++) acc[i][j] = 0.f;

    // loader indices
    const int arow = tid >> 2;          // 0..63
    const int akq  = (tid & 3) * 4;     // 0,4,8,12
    const int wrow = tid >> 1;          // 0..127
    const int wkq  = (tid & 1) * 8;     // 0,8

    for (int kc = 0; kc < IN; kc += 16) {
        __syncthreads();
        // ---- load A tile (64x16) ----
        {
            const int grow = row0 + arow;
            float4 av = make_float4(0.f, 0.f, 0.f, 0.f);
            if (grow < nrows) {
                const int kk = kc + akq;
                const float* ap;
                if (SPLIT) {
                    ap = (kk < 128) ? &A[grow * 128 + kk]
                                    : &A2[grow * 128 + (kk - 128)];
                } else {
                    ap = &A[grow * IN + kk];
                }
                av = *(const float4*)ap;
            }
            As[akq + 0][arow] = av.x;
            As[akq + 1][arow] = av.y;
            As[akq + 2][arow] = av.z;
            As[akq + 3][arow] = av.w;
        }
        // ---- load W tile (128x16) ----
        {
            const float* wp = &W[(size_t)(col0 + wrow) * IN + kc + wkq];
            float4 w0 = *(const float4*)wp;
            float4 w1 = *(const float4*)(wp + 4);
            Ws[wkq + 0][wrow] = w0.x;
            Ws[wkq + 1][wrow] = w0.y;
            Ws[wkq + 2][wrow] = w0.z;
            Ws[wkq + 3][wrow] = w0.w;
            Ws[wkq + 4][wrow] = w1.x;
            Ws[wkq + 5][wrow] = w1.y;
            Ws[wkq + 6][wrow] = w1.z;
            Ws[wkq + 7][wrow] = w1.w;
        }
        __syncthreads();
        // ---- compute ----
#pragma unroll
        for (int k = 0; k < 16; k++) {
            float a[8];
#pragma unroll
            for (int i = 0; i < 8; i++) a[i] = As[k][trow * 8 + i];
            const float4 wv = *(const float4*)&Ws[k][tcol * 4];
#pragma unroll
            for (int i = 0; i < 8; i++) {
                acc[i][0] += a[i] * wv.x;
                acc[i][1] += a[i] * wv.y;
                acc[i][2] += a[i] * wv.z;
                acc[i][3] += a[i] * wv.w;
            }
        }
    }

    // ---- epilogue ----
    const int col = col0 + tcol * 4;
    const float4 bv = *(const float4*)&bias[col];
    float4 gv = make_float4(1.f, 1.f, 1.f, 1.f);
    float4 bb = make_float4(0.f, 0.f, 0.f, 0.f);
    if (LN) {
        gv = *(const float4*)&lng[col];
        bb = *(const float4*)&lnb[col];
    }
#pragma unroll
    for (int i = 0; i < 8; i++) {
        const int grow = row0 + trow * 8 + i;   // uniform across warp
        const bool ok = (grow < nrows);
        float v0 = acc[i][0] + bv.x;
        float v1 = acc[i][1] + bv.y;
        float v2 = acc[i][2] + bv.z;
        float v3 = acc[i][3] + bv.w;
        if (RELU) {
            v0 = fmaxf(v0, 0.f); v1 = fmaxf(v1, 0.f);
            v2 = fmaxf(v2, 0.f); v3 = fmaxf(v3, 0.f);
        }
        if (RES) {
            if (ok) {
                const float4 r = *(const float4*)&res[(size_t)grow * OUT + col];
                v0 += r.x; v1 += r.y; v2 += r.z; v3 += r.w;
            }
        }
        if (LN) {
            float s  = v0 + v1 + v2 + v3;
            float s2 = v0 * v0 + v1 * v1 + v2 * v2 + v3 * v3;
#pragma unroll
            for (int m = 16; m; m >>= 1) {
                s  += __shfl_xor_sync(0xffffffffu, s,  m);
                s2 += __shfl_xor_sync(0xffffffffu, s2, m);
            }
            const float mean = s * (1.f / 128.f);
            const float var  = s2 * (1.f / 128.f) - mean * mean;
            const float rstd = rsqrtf(var + 1e-5f);
            v0 = (v0 - mean) * rstd * gv.x + bb.x;
            v1 = (v1 - mean) * rstd * gv.y + bb.y;
            v2 = (v2 - mean) * rstd * gv.z + bb.z;
            v3 = (v3 - mean) * rstd * gv.w + bb.w;
        }
        if (ok) {
            *(float4*)&C[(size_t)grow * OUT + col] = make_float4(v0, v1, v2, v3);
        }
    }
}

// ---------------- attention: warp per node ----------------
// qkv: [N,384] (q|k|v). For node n: scores over K=20 sampled keys,
// 4 heads of 32. lane owns cols [4*lane, 4*lane+4), head = lane/8.
__global__ __launch_bounds__(256) void attn_kernel(
    const float* __restrict__ qkv, const int* __restrict__ samp,
    float* __restrict__ out, int n)
{
    const int warp = (blockIdx.x * blockDim.x + threadIdx.x) >> 5;
    const int lane = threadIdx.x & 31;
    if (warp >= n) return;
    const int node = warp;
    const int c0 = lane * 4;

    const float4 q = *(const float4*)&qkv[node * 384 + c0];
    int idxs[KATT];
#pragma unroll
    for (int j = 0; j < KATT; j++) idxs[j] = samp[node * KATT + j];

    const float scale = 0.17677669529663687f;   // 1/sqrt(32)
    float s[KATT];
    float mx = -1e30f;
#pragma unroll
    for (int j = 0; j < KATT; j++) {
        const float4 kv = *(const float4*)&qkv[idxs[j] * 384 + 128 + c0];
        float d = q.x * kv.x + q.y * kv.y + q.z * kv.z + q.w * kv.w;
        d += __shfl_xor_sync(0xffffffffu, d, 1);
        d += __shfl_xor_sync(0xffffffffu, d, 2);
        d += __shfl_xor_sync(0xffffffffu, d, 4);
        s[j] = d * scale;
        mx = fmaxf(mx, s[j]);
    }
    float sum = 0.f;
#pragma unroll
    for (int j = 0; j < KATT; j++) { s[j] = expf(s[j] - mx); sum += s[j]; }
    const float inv = 1.f / sum;

    float4 acc = make_float4(0.f, 0.f, 0.f, 0.f);
#pragma unroll
    for (int j = 0; j < KATT; j++) {
        const float4 vv = *(const float4*)&qkv[idxs[j] * 384 + 256 + c0];
        const float a = s[j] * inv;
        acc.x += a * vv.x; acc.y += a * vv.y;
        acc.z += a * vv.z; acc.w += a * vv.w;
    }
    *(float4*)&out[node * 128 + c0] = acc;
}

// ---------------- GNN CSR build + aggregate ----------------
__global__ void hist_kernel(const int* __restrict__ src, int* __restrict__ deg, int e) {
    const int i = blockIdx.x * blockDim.x + threadIdx.x;
    if (i < e) atomicAdd(&deg[src[i]], 1);
}

__global__ void scan_kernel(const int* __restrict__ deg, int* __restrict__ off, int n) {
    __shared__ int sh[32];
    __shared__ int carry_s;
    const int tid = threadIdx.x;
    const int lane = tid & 31, wid = tid >> 5;
    if (tid == 0) carry_s = 0;
    __syncthreads();
    for (int base = 0; base < n; base += 1024) {
        const int i = base + tid;
        const int v = (i < n) ? deg[i] : 0;
        int x = v;
#pragma unroll
        for (int d = 1; d < 32; d <<= 1) {
            const int t = __shfl_up_sync(0xffffffffu, x, d);
            if (lane >= d) x += t;
        }
        if (lane == 31) sh[wid] = x;
        __syncthreads();
        if (wid == 0) {
            int w = sh[lane];
#pragma unroll
            for (int d = 1; d < 32; d <<= 1) {
                const int t = __shfl_up_sync(0xffffffffu, w, d);
                if (lane >= d) w += t;
            }
            sh[lane] = w;
        }
        __syncthreads();
        const int incl = x + (wid > 0 ? sh[wid - 1] : 0) + carry_s;
        if (i < n) off[i] = incl - v;   // exclusive
        __syncthreads();
        if (tid == 1023) carry_s = incl;
        __syncthreads();
    }
    if (tid == 0) off[n] = carry_s;
}

__global__ void scatter_kernel(const int* __restrict__ src, const int* __restrict__ dst,
                               const int* __restrict__ off, int* __restrict__ cnt,
                               int* __restrict__ csr, int e) {
    const int i = blockIdx.x * blockDim.x + threadIdx.x;
    if (i < e) {
        const int s = src[i];
        const int pos = off[s] + atomicAdd(&cnt[s], 1);
        csr[pos] = dst[i];
    }
}

// warp per node: neigh[n] = sum over edges of h[dst]
__global__ __launch_bounds__(256) void agg_kernel(
    const float* __restrict__ h, const int* __restrict__ off,
    const int* __restrict__ csr, float* __restrict__ neigh, int n)
{
    const int warp = (blockIdx.x * blockDim.x + threadIdx.x) >> 5;
    const int lane = threadIdx.x & 31;
    if (warp >= n) return;
    const int beg = off[warp], end = off[warp + 1];
    float4 acc = make_float4(0.f, 0.f, 0.f, 0.f);
    for (int e = beg; e < end; e++) {
        const int d = csr[e];
        const float4 hv = *(const float4*)&h[d * 128 + lane * 4];
        acc.x += hv.x; acc.y += hv.y; acc.z += hv.z; acc.w += hv.w;
    }
    *(float4*)&neigh[warp * 128 + lane * 4] = acc;
}

// ---------------- host orchestration ----------------
extern "C" void kernel_launch(void* const* d_in, const int* in_sizes, int n_in,
                              void* d_out, int out_size)
{
    const float* x       = (const float*)d_in[0];
    const int*   samples = (const int*)d_in[1];
    const int*   esrc    = (const int*)d_in[2];
    const int*   edst    = (const int*)d_in[3];
    const float* t_in_w  = (const float*)d_in[4];
    const float* t_in_b  = (const float*)d_in[5];
    const float* t_out_w = (const float*)d_in[6];
    const float* t_out_b = (const float*)d_in[7];
    const float* t_f_w1  = (const float*)d_in[8];
    const float* t_f_b1  = (const float*)d_in[9];
    const float* t_f_w2  = (const float*)d_in[10];
    const float* t_f_b2  = (const float*)d_in[11];
    const float* ln1g    = (const float*)d_in[12];
    const float* ln1b    = (const float*)d_in[13];
    const float* ln2g    = (const float*)d_in[14];
    const float* ln2b    = (const float*)d_in[15];
    const float* gw      = (const float*)d_in[16];
    const float* gb      = (const float*)d_in[17];
    const float* glng    = (const float*)d_in[18];
    const float* glnb    = (const float*)d_in[19];

    float *pqkv, *pattn, *pa, *ptmp, *ph, *ph2, *pneigh;
    int *pdeg, *poff, *pcnt, *pcsr;
    cudaGetSymbolAddress((void**)&pqkv,   g_qkv);
    cudaGetSymbolAddress((void**)&pattn,  g_attn);
    cudaGetSymbolAddress((void**)&pa,     g_a);
    cudaGetSymbolAddress((void**)&ptmp,   g_tmp);
    cudaGetSymbolAddress((void**)&ph,     g_h);
    cudaGetSymbolAddress((void**)&ph2,    g_h2);
    cudaGetSymbolAddress((void**)&pneigh, g_neigh);
    cudaGetSymbolAddress((void**)&pdeg,   g_deg);
    cudaGetSymbolAddress((void**)&poff,   g_off);
    cudaGetSymbolAddress((void**)&pcnt,   g_cnt);
    cudaGetSymbolAddress((void**)&pcsr,   g_csr);

    const int n = NN;
    const int e = EE;
    const int GX = (n + 63) / 64;
    const int WARP_GRID = (n + 7) / 8;       // 8 warps / 256-thread block
    const int EG = (e + 255) / 256;

    // ---- build CSR once (reused by both GNN layers) ----
    cudaMemsetAsync(pdeg, 0, n * sizeof(int));
    cudaMemsetAsync(pcnt, 0, n * sizeof(int));
    hist_kernel<<<EG, 256>>>(esrc, pdeg, e);
    scan_kernel<<<1, 1024>>>(pdeg, poff, n);
    scatter_kernel<<<EG, 256>>>(esrc, edst, poff, pcnt, pcsr, e);

    // ---- transformer layer ----
    auto run_trans = [&](const float* hin, float* hout, int i) {
        gemm_fused<128, 384, false, false, false, false><<<dim3(GX, 3), 256>>>(
            hin, nullptr, t_in_w + (size_t)i * 384 * 128, t_in_b + i * 384,
            nullptr, nullptr, nullptr, pqkv, n);
        attn_kernel<<<WARP_GRID, 256>>>(pqkv, samples, pattn, n);
        gemm_fused<128, 128, false, true, true, false><<<dim3(GX, 1), 256>>>(
            pattn, nullptr, t_out_w + (size_t)i * 128 * 128, t_out_b + i * 128,
            hin, ln1g + i * 128, ln1b + i * 128, pa, n);
        gemm_fused<128, 512, true, false, false, false><<<dim3(GX, 4), 256>>>(
            pa, nullptr, t_f_w1 + (size_t)i * 512 * 128, t_f_b1 + i * 512,
            nullptr, nullptr, nullptr, ptmp, n);
        gemm_fused<512, 128, false, true, true, false><<<dim3(GX, 1), 256>>>(
            ptmp, nullptr, t_f_w2 + (size_t)i * 128 * 512, t_f_b2 + i * 128,
            pa, ln2g + i * 128, ln2b + i * 128, hout, n);
    };

    // ---- GNN layer ----
    auto run_gnn = [&](const float* hin, float* hout, int i) {
        agg_kernel<<<WARP_GRID, 256>>>(hin, poff, pcsr, pneigh, n);
        gemm_fused<256, 128, true, true, true, true><<<dim3(GX, 1), 256>>>(
            hin, pneigh, gw + (size_t)i * 128 * 256, gb + i * 128,
            hin, glng + i * 128, glnb + i * 128, hout, n);
    };

    run_trans(x, ph, 0);
    run_gnn(ph, ph2, 0);
    run_trans(ph2, ph, 1);
    run_gnn(ph, ph2, 1);
    run_trans(ph2, (float*)d_out, 2);
}

// round 2
// speedup vs baseline: 1.6307x; 1.6307x over previous
#include <cuda_runtime.h>

#define NN 50000
#define DD 128
#define EE 1600000
#define KATT 20

// ---------------- scratch (static device allocations) ----------------
__device__ float g_qkv[NN * 384];
__device__ float g_attn[NN * DD];
__device__ float g_a[NN * DD];
__device__ float g_tmp[NN * 512];
__device__ float g_h[NN * DD];
__device__ float g_h2[NN * DD];
__device__ float g_neigh[NN * DD];
__device__ int   g_deg[NN];
__device__ int   g_off[NN + 1];
__device__ int   g_cnt[NN];
__device__ int   g_csr[EE];

// ---------------- TF32 helpers ----------------
__device__ __forceinline__ unsigned tf32cvt(float x) {
    unsigned r;
    asm("cvt.rna.tf32.f32 %0, %1;" : "=r"(r) : "f"(x));
    return r;
}

__device__ __forceinline__ void mma_tf32(float c[4], const unsigned a[4],
                                         unsigned b0, unsigned b1) {
    asm("mma.sync.aligned.m16n8k8.row.col.f32.tf32.tf32.f32 "
        "{%0,%1,%2,%3}, {%4,%5,%6,%7}, {%8,%9}, {%0,%1,%2,%3};\n"
        : "+f"(c[0]), "+f"(c[1]), "+f"(c[2]), "+f"(c[3])
        : "r"(a[0]), "r"(a[1]), "r"(a[2]), "r"(a[3]), "r"(b0), "r"(b1));
}

// ---------------- fused TF32 tensor-core GEMM ----------------
// C = epi(A @ W^T + b). W is [OUT, IN] row-major.
// Block tile 128x128, 256 threads = 8 warps (4 m-warps x 2 n-warps),
// warp tile 32x64 (2 m-frags x 8 n-frags of m16n8k8).
// Smem k-layout permuted within each 8-k group: pos = (k%4)*2 + (k/4),
// row stride 40 floats (==8 mod 32) -> conflict-free 64-bit frag loads.
// LN valid only when OUT==128 (full row within block; cross-warp via smem).
// SPLIT: logical A = concat(A, A2) along K (each row stride 128).
template <int IN, int OUT, bool RELU, bool RES, bool LN, bool SPLIT>
__global__ __launch_bounds__(256, 2) void gemm_tc(
    const float* __restrict__ A, const float* __restrict__ A2,
    const float* __restrict__ W, const float* __restrict__ bias,
    const float* __restrict__ res,
    const float* __restrict__ lng, const float* __restrict__ lnb,
    float* __restrict__ C, int nrows)
{
    constexpr int SST = 40;                    // smem row stride (floats)
    __shared__ unsigned As[128 * SST];
    __shared__ unsigned Ws[128 * SST];
    __shared__ float2   lnp[2][128];           // per-warp_n LN partials

    const int tid    = threadIdx.x;
    const int lane   = tid & 31;
    const int warp   = tid >> 5;
    const int warp_m = warp & 3;               // 0..3
    const int warp_n = warp >> 2;              // 0..1
    const int g      = lane >> 2;              // 0..7
    const int t      = lane & 3;               // 0..3
    const int row0   = blockIdx.x * 128;
    const int col0   = blockIdx.y * 128;
    const int colb   = warp_n * 64;

    float acc[2][8][4];
#pragma unroll
    for (int fm = 0; fm < 2; fm++)
#pragma unroll
        for (int nf = 0; nf < 8; nf++)
#pragma unroll
            for (int r = 0; r < 4; r++) acc[fm][nf][r] = 0.f;

    // loader: idx over 128 rows x 8 float4-quads
    for (int kc = 0; kc < IN; kc += 32) {
        __syncthreads();
#pragma unroll
        for (int it = 0; it < 4; it++) {
            const int idx = it * 256 + tid;
            const int r   = idx >> 3;           // 0..127
            const int cq  = (idx & 7) * 4;      // 0,4,...,28
            const int base8 = cq & ~7;          // 8-group base
            const int half  = (cq & 4) >> 2;    // 0 or 1 -> perm offset

            // ---- A tile ----
            float4 av = make_float4(0.f, 0.f, 0.f, 0.f);
            const int grow = row0 + r;
            if (grow < nrows) {
                const int kk = kc + cq;
                const float* ap;
                if (SPLIT) {
                    ap = (kk < 128) ? &A[(size_t)grow * 128 + kk]
                                    : &A2[(size_t)grow * 128 + (kk - 128)];
                } else {
                    ap = &A[(size_t)grow * IN + kk];
                }
                av = *(const float4*)ap;
            }
            unsigned* as = &As[r * SST + base8 + half];
            as[0] = tf32cvt(av.x);
            as[2] = tf32cvt(av.y);
            as[4] = tf32cvt(av.z);
            as[6] = tf32cvt(av.w);

            // ---- W tile ----
            const float4 wv = *(const float4*)&W[(size_t)(col0 + r) * IN + kc + cq];
            unsigned* ws = &Ws[r * SST + base8 + half];
            ws[0] = tf32cvt(wv.x);
            ws[2] = tf32cvt(wv.y);
            ws[4] = tf32cvt(wv.z);
            ws[6] = tf32cvt(wv.w);
        }
        __syncthreads();

#pragma unroll
        for (int ks = 0; ks < 4; ks++) {
            const int kp = ks * 8 + 2 * t;
            unsigned a[2][4];
#pragma unroll
            for (int fm = 0; fm < 2; fm++) {
                const int rb = warp_m * 32 + fm * 16;
                const uint2 p0 = *(const uint2*)&As[(rb + g) * SST + kp];
                const uint2 p1 = *(const uint2*)&As[(rb + g + 8) * SST + kp];
                a[fm][0] = p0.x; a[fm][1] = p1.x;
                a[fm][2] = p0.y; a[fm][3] = p1.y;
            }
#pragma unroll
            for (int nf = 0; nf < 8; nf++) {
                const uint2 bb = *(const uint2*)&Ws[(colb + nf * 8 + g) * SST + kp];
                mma_tf32(acc[0][nf], a[0], bb.x, bb.y);
                mma_tf32(acc[1][nf], a[1], bb.x, bb.y);
            }
        }
    }

    // ---------------- epilogue ----------------
    // thread holds rows: warp_m*32 + fm*16 + ro*8 + g, cols colb + nf*8 + 2t..2t+1
    float2 bias2[8];
#pragma unroll
    for (int nf = 0; nf < 8; nf++)
        bias2[nf] = *(const float2*)&bias[col0 + colb + nf * 8 + 2 * t];

    // pass 1: bias/relu/res, LN partials
#pragma unroll
    for (int fm = 0; fm < 2; fm++) {
#pragma unroll
        for (int ro = 0; ro < 2; ro++) {
            const int row  = warp_m * 32 + fm * 16 + ro * 8 + g;
            const int grow = row0 + row;
            const bool ok  = (grow < nrows);
            float s = 0.f, s2 = 0.f;
#pragma unroll
            for (int nf = 0; nf < 8; nf++) {
                float v0 = acc[fm][nf][ro * 2 + 0] + bias2[nf].x;
                float v1 = acc[fm][nf][ro * 2 + 1] + bias2[nf].y;
                if (RELU) { v0 = fmaxf(v0, 0.f); v1 = fmaxf(v1, 0.f); }
                if (RES && ok) {
                    const float2 rv = *(const float2*)
                        &res[(size_t)grow * OUT + col0 + colb + nf * 8 + 2 * t];
                    v0 += rv.x; v1 += rv.y;
                }
                acc[fm][nf][ro * 2 + 0] = v0;
                acc[fm][nf][ro * 2 + 1] = v1;
                if (LN) { s += v0 + v1; s2 += v0 * v0 + v1 * v1; }
            }
            if (LN) {
                s  += __shfl_xor_sync(0xffffffffu, s, 1);
                s2 += __shfl_xor_sync(0xffffffffu, s2, 1);
                s  += __shfl_xor_sync(0xffffffffu, s, 2);
                s2 += __shfl_xor_sync(0xffffffffu, s2, 2);
                if (t == 0) lnp[warp_n][row] = make_float2(s, s2);
            }
        }
    }
    if (LN) __syncthreads();

    // pass 2: normalize + write
#pragma unroll
    for (int fm = 0; fm < 2; fm++) {
#pragma unroll
        for (int ro = 0; ro < 2; ro++) {
            const int row  = warp_m * 32 + fm * 16 + ro * 8 + g;
            const int grow = row0 + row;
            if (grow >= nrows) continue;
            float mean = 0.f, rstd = 1.f;
            if (LN) {
                const float2 p0 = lnp[0][row];
                const float2 p1 = lnp[1][row];
                const float s  = p0.x + p1.x;
                const float s2 = p0.y + p1.y;
                mean = s * (1.f / 128.f);
                const float var = s2 * (1.f / 128.f) - mean * mean;
                rstd = rsqrtf(var + 1e-5f);
            }
#pragma unroll
            for (int nf = 0; nf < 8; nf++) {
                const int col = col0 + colb + nf * 8 + 2 * t;
                float v0 = acc[fm][nf][ro * 2 + 0];
                float v1 = acc[fm][nf][ro * 2 + 1];
                if (LN) {
                    const float2 gv = *(const float2*)&lng[col];
                    const float2 bb = *(const float2*)&lnb[col];
                    v0 = (v0 - mean) * rstd * gv.x + bb.x;
                    v1 = (v1 - mean) * rstd * gv.y + bb.y;
                }
                *(float2*)&C[(size_t)grow * OUT + col] = make_float2(v0, v1);
            }
        }
    }
}

// ---------------- attention: warp per node ----------------
__global__ __launch_bounds__(256) void attn_kernel(
    const float* __restrict__ qkv, const int* __restrict__ samp,
    float* __restrict__ out, int n)
{
    const int warp = (blockIdx.x * blockDim.x + threadIdx.x) >> 5;
    const int lane = threadIdx.x & 31;
    if (warp >= n) return;
    const int node = warp;
    const int c0 = lane * 4;

    const float4 q = *(const float4*)&qkv[node * 384 + c0];
    int idxs[KATT];
#pragma unroll
    for (int j = 0; j < KATT; j++) idxs[j] = samp[node * KATT + j];

    const float scale = 0.17677669529663687f;   // 1/sqrt(32)
    float s[KATT];
    float mx = -1e30f;
#pragma unroll
    for (int j = 0; j < KATT; j++) {
        const float4 kv = *(const float4*)&qkv[idxs[j] * 384 + 128 + c0];
        float d = q.x * kv.x + q.y * kv.y + q.z * kv.z + q.w * kv.w;
        d += __shfl_xor_sync(0xffffffffu, d, 1);
        d += __shfl_xor_sync(0xffffffffu, d, 2);
        d += __shfl_xor_sync(0xffffffffu, d, 4);
        s[j] = d * scale;
        mx = fmaxf(mx, s[j]);
    }
    float sum = 0.f;
#pragma unroll
    for (int j = 0; j < KATT; j++) { s[j] = expf(s[j] - mx); sum += s[j]; }
    const float inv = 1.f / sum;

    float4 a = make_float4(0.f, 0.f, 0.f, 0.f);
#pragma unroll
    for (int j = 0; j < KATT; j++) {
        const float4 vv = *(const float4*)&qkv[idxs[j] * 384 + 256 + c0];
        const float w = s[j] * inv;
        a.x += w * vv.x; a.y += w * vv.y;
        a.z += w * vv.z; a.w += w * vv.w;
    }
    *(float4*)&out[node * 128 + c0] = a;
}

// ---------------- GNN CSR build + aggregate ----------------
__global__ void hist_kernel(const int* __restrict__ src, int* __restrict__ deg, int e) {
    const int i = blockIdx.x * blockDim.x + threadIdx.x;
    if (i < e) atomicAdd(&deg[src[i]], 1);
}

__global__ void scan_kernel(const int* __restrict__ deg, int* __restrict__ off, int n) {
    __shared__ int sh[32];
    __shared__ int carry_s;
    const int tid = threadIdx.x;
    const int lane = tid & 31, wid = tid >> 5;
    if (tid == 0) carry_s = 0;
    __syncthreads();
    for (int base = 0; base < n; base += 1024) {
        const int i = base + tid;
        const int v = (i < n) ? deg[i] : 0;
        int x = v;
#pragma unroll
        for (int d = 1; d < 32; d <<= 1) {
            const int t = __shfl_up_sync(0xffffffffu, x, d);
            if (lane >= d) x += t;
        }
        if (lane == 31) sh[wid] = x;
        __syncthreads();
        if (wid == 0) {
            int w = sh[lane];
#pragma unroll
            for (int d = 1; d < 32; d <<= 1) {
                const int t = __shfl_up_sync(0xffffffffu, w, d);
                if (lane >= d) w += t;
            }
            sh[lane] = w;
        }
        __syncthreads();
        const int incl = x + (wid > 0 ? sh[wid - 1] : 0) + carry_s;
        if (i < n) off[i] = incl - v;   // exclusive
        __syncthreads();
        if (tid == 1023) carry_s = incl;
        __syncthreads();
    }
    if (tid == 0) off[n] = carry_s;
}

__global__ void scatter_kernel(const int* __restrict__ src, const int* __restrict__ dst,
                               const int* __restrict__ off, int* __restrict__ cnt,
                               int* __restrict__ csr, int e) {
    const int i = blockIdx.x * blockDim.x + threadIdx.x;
    if (i < e) {
        const int s = src[i];
        const int pos = off[s] + atomicAdd(&cnt[s], 1);
        csr[pos] = dst[i];
    }
}

__global__ __launch_bounds__(256) void agg_kernel(
    const float* __restrict__ h, const int* __restrict__ off,
    const int* __restrict__ csr, float* __restrict__ neigh, int n)
{
    const int warp = (blockIdx.x * blockDim.x + threadIdx.x) >> 5;
    const int lane = threadIdx.x & 31;
    if (warp >= n) return;
    const int beg = off[warp], end = off[warp + 1];
    float4 acc = make_float4(0.f, 0.f, 0.f, 0.f);
    for (int e = beg; e < end; e++) {
        const int d = csr[e];
        const float4 hv = *(const float4*)&h[d * 128 + lane * 4];
        acc.x += hv.x; acc.y += hv.y; acc.z += hv.z; acc.w += hv.w;
    }
    *(float4*)&neigh[warp * 128 + lane * 4] = acc;
}

// ---------------- host orchestration ----------------
extern "C" void kernel_launch(void* const* d_in, const int* in_sizes, int n_in,
                              void* d_out, int out_size)
{
    const float* x       = (const float*)d_in[0];
    const int*   samples = (const int*)d_in[1];
    const int*   esrc    = (const int*)d_in[2];
    const int*   edst    = (const int*)d_in[3];
    const float* t_in_w  = (const float*)d_in[4];
    const float* t_in_b  = (const float*)d_in[5];
    const float* t_out_w = (const float*)d_in[6];
    const float* t_out_b = (const float*)d_in[7];
    const float* t_f_w1  = (const float*)d_in[8];
    const float* t_f_b1  = (const float*)d_in[9];
    const float* t_f_w2  = (const float*)d_in[10];
    const float* t_f_b2  = (const float*)d_in[11];
    const float* ln1g    = (const float*)d_in[12];
    const float* ln1b    = (const float*)d_in[13];
    const float* ln2g    = (const float*)d_in[14];
    const float* ln2b    = (const float*)d_in[15];
    const float* gw      = (const float*)d_in[16];
    const float* gb      = (const float*)d_in[17];
    const float* glng    = (const float*)d_in[18];
    const float* glnb    = (const float*)d_in[19];

    float *pqkv, *pattn, *pa, *ptmp, *ph, *ph2, *pneigh;
    int *pdeg, *poff, *pcnt, *pcsr;
    cudaGetSymbolAddress((void**)&pqkv,   g_qkv);
    cudaGetSymbolAddress((void**)&pattn,  g_attn);
    cudaGetSymbolAddress((void**)&pa,     g_a);
    cudaGetSymbolAddress((void**)&ptmp,   g_tmp);
    cudaGetSymbolAddress((void**)&ph,    g_h);
    cudaGetSymbolAddress((void**)&ph2,   g_h2);
    cudaGetSymbolAddress((void**)&pneigh, g_neigh);
    cudaGetSymbolAddress((void**)&pdeg,   g_deg);
    cudaGetSymbolAddress((void**)&poff,   g_off);
    cudaGetSymbolAddress((void**)&pcnt,   g_cnt);
    cudaGetSymbolAddress((void**)&pcsr,   g_csr);

    const int n = NN;
    const int e = EE;
    const int GX = (n + 127) / 128;
    const int WARP_GRID = (n + 7) / 8;       // 8 warps / 256-thread block
    const int EG = (e + 255) / 256;

    // ---- build CSR once (reused by both GNN layers) ----
    cudaMemsetAsync(pdeg, 0, n * sizeof(int));
    cudaMemsetAsync(pcnt, 0, n * sizeof(int));
    hist_kernel<<<EG, 256>>>(esrc, pdeg, e);
    scan_kernel<<<1, 1024>>>(pdeg, poff, n);
    scatter_kernel<<<EG, 256>>>(esrc, edst, poff, pcnt, pcsr, e);

    // ---- transformer layer ----
    auto run_trans = [&](const float* hin, float* hout, int i) {
        gemm_tc<128, 384, false, false, false, false><<<dim3(GX, 3), 256>>>(
            hin, nullptr, t_in_w + (size_t)i * 384 * 128, t_in_b + i * 384,
            nullptr, nullptr, nullptr, pqkv, n);
        attn_kernel<<<WARP_GRID, 256>>>(pqkv, samples, pattn, n);
        gemm_tc<128, 128, false, true, true, false><<<dim3(GX, 1), 256>>>(
            pattn, nullptr, t_out_w + (size_t)i * 128 * 128, t_out_b + i * 128,
            hin, ln1g + i * 128, ln1b + i * 128, pa, n);
        gemm_tc<128, 512, true, false, false, false><<<dim3(GX, 4), 256>>>(
            pa, nullptr, t_f_w1 + (size_t)i * 512 * 128, t_f_b1 + i * 512,
            nullptr, nullptr, nullptr, ptmp, n);
        gemm_tc<512, 128, false, true, true, false><<<dim3(GX, 1), 256>>>(
            ptmp, nullptr, t_f_w2 + (size_t)i * 128 * 512, t_f_b2 + i * 128,
            pa, ln2g + i * 128, ln2b + i * 128, hout, n);
    };

    // ---- GNN layer ----
    auto run_gnn = [&](const float* hin, float* hout, int i) {
        agg_kernel<<<WARP_GRID, 256>>>(hin, poff, pcsr, pneigh, n);
        gemm_tc<256, 128, true, true, true, true><<<dim3(GX, 1), 256>>>(
            hin, pneigh, gw + (size_t)i * 128 * 256, gb + i * 128,
            hin, glng + i * 128, glnb + i * 128, hout, n);
    };

    run_trans(x, ph, 0);
    run_gnn(ph, ph2, 0);
    run_trans(ph2, ph, 1);
    run_gnn(ph, ph2, 1);
    run_trans(ph2, (float*)d_out, 2);
}

// round 3
// speedup vs baseline: 1.9056x; 1.1686x over previous
#include <cuda_runtime.h>

#define NN 50000
#define DD 128
#define EE 1600000
#define KATT 20

// ---------------- scratch (static device allocations) ----------------
__device__ float g_qkv[NN * 384];
__device__ float g_attn[NN * DD];
__device__ float g_a[NN * DD];
__device__ float g_tmp[NN * 512];
__device__ float g_h[NN * DD];
__device__ float g_h2[NN * DD];
__device__ float g_neigh[NN * DD];
__device__ float g_hx[NN * DD];
__device__ int   g_deg[NN];
__device__ int   g_off[NN + 1];
__device__ int   g_cnt[NN];
__device__ int   g_csr[EE];

// converted (tf32-rounded, permuted) parameters
__device__ float g_wqkv[3 * 384 * 128];
__device__ float g_wout[3 * 128 * 128];
__device__ float g_wf1 [3 * 512 * 128];
__device__ float g_wf2 [3 * 128 * 512];
__device__ float g_wg  [2 * 128 * 256];
__device__ float g_bqkv[3 * 384];
__device__ float g_bout[3 * 128];
__device__ float g_bf1 [3 * 512];
__device__ float g_bf2 [3 * 128];
__device__ float g_l1g [3 * 128];
__device__ float g_l1b [3 * 128];
__device__ float g_l2g [3 * 128];
__device__ float g_l2b [3 * 128];
__device__ float g_bg  [2 * 128];
__device__ float g_gg  [2 * 128];
__device__ float g_gb  [2 * 128];

// ---------------- helpers ----------------
__device__ __forceinline__ unsigned tf32cvt(float x) {
    unsigned r;
    asm("cvt.rna.tf32.f32 %0, %1;" : "=r"(r) : "f"(x));
    return r;
}
__device__ __forceinline__ float tf32r(float x) { return __uint_as_float(tf32cvt(x)); }

// within-8 column permutation for mma k-fragments (logical -> physical)
__device__ __forceinline__ int gperm(int i) {
    return (i & ~7) + ((i & 3) << 1) + ((i & 4) >> 2);
}

__device__ __forceinline__ void mma_tf32(float c[4], const unsigned a[4],
                                         unsigned b0, unsigned b1) {
    asm("mma.sync.aligned.m16n8k8.row.col.f32.tf32.tf32.f32 "
        "{%0,%1,%2,%3}, {%4,%5,%6,%7}, {%8,%9}, {%0,%1,%2,%3};\n"
        : "+f"(c[0]), "+f"(c[1]), "+f"(c[2]), "+f"(c[3])
        : "r"(a[0]), "r"(a[1]), "r"(a[2]), "r"(a[3]), "r"(b0), "r"(b1));
}

__device__ __forceinline__ void cp16(void* sdst, const void* gsrc, int sz) {
    unsigned s = (unsigned)__cvta_generic_to_shared(sdst);
    asm volatile("cp.async.cg.shared.global [%0], [%1], 16, %2;\n"
                 :: "r"(s), "l"(gsrc), "r"(sz));
}
__device__ __forceinline__ void cp_commit() {
    asm volatile("cp.async.commit_group;\n");
}
__device__ __forceinline__ void cp_wait1() {
    asm volatile("cp.async.wait_group 1;\n");
}
__device__ __forceinline__ void cp_wait0() {
    asm volatile("cp.async.wait_group 0;\n");
}

// ---------------- parameter conversion ----------------
struct PEnt { const float* s; float* d; int rows; int cols; int mode; };
struct PTab { PEnt e[48]; };

__global__ void param_conv(PTab t, int n) {
    const int ei = blockIdx.y;
    if (ei >= n) return;
    const PEnt en = t.e[ei];
    const int total = en.rows * en.cols;
    for (int i = blockIdx.x * blockDim.x + threadIdx.x; i < total;
         i += gridDim.x * blockDim.x) {
        if (en.mode == 0) {           // matrix: permute both dims + tf32 round
            const int r = i / en.cols, c = i % en.cols;
            en.d[(size_t)gperm(r) * en.cols + gperm(c)] = tf32r(en.s[i]);
        } else {                      // vector: permute only
            en.d[gperm(i)] = en.s[i];
        }
    }
}

__global__ void conv_x(const float* __restrict__ x, float* __restrict__ o) {
    const int i = blockIdx.x * blockDim.x + threadIdx.x;
    if (i < NN * 128) {
        const int r = i >> 7, c = i & 127;
        o[(r << 7) + gperm(c)] = tf32r(x[i]);
    }
}

// ---------------- fused TF32 tensor-core GEMM (cp.async pipelined) ----------------
// All operands live in "permuted world" (within-8 col permutation) and are
// pre-rounded to tf32, so smem tiles are raw byte copies of gmem.
// Block 128x128, 8 warps (4m x 2n), warp tile 32x64, BK=32, 2-stage cp.async.
// OMODE: 1 = store tf32-rounded (activation), 2 = final store (inverse-permute cols).
template <int IN, int OUT, bool RELU, bool RES, bool LN, bool SPLIT, int OMODE>
__global__ __launch_bounds__(256, 2) void gemm_tc(
    const float* __restrict__ A, const float* __restrict__ A2,
    const float* __restrict__ W, const float* __restrict__ bias,
    const float* __restrict__ res,
    const float* __restrict__ lng, const float* __restrict__ lnb,
    float* __restrict__ C, int nrows)
{
    constexpr int SST = 40;                      // smem row stride (floats)
    extern __shared__ float smem[];
    float* Asm[2] = { smem,             smem + 128 * SST };
    float* Wsm[2] = { smem + 2 * 128 * SST, smem + 3 * 128 * SST };
    float2* lnp   = (float2*)(smem + 4 * 128 * SST);   // [2][128]

    const int tid    = threadIdx.x;
    const int lane   = tid & 31;
    const int warp   = tid >> 5;
    const int warp_m = warp & 3;
    const int warp_n = warp >> 2;
    const int g      = lane >> 2;
    const int t      = lane & 3;
    const int row0   = blockIdx.x * 128;
    const int col0   = blockIdx.y * 128;
    const int colb   = warp_n * 64;

    float acc[2][8][4];
#pragma unroll
    for (int fm = 0; fm < 2; fm++)
#pragma unroll
        for (int nf = 0; nf < 8; nf++)
#pragma unroll
            for (int r = 0; r < 4; r++) acc[fm][nf][r] = 0.f;

    constexpr int NCH = IN / 32;
    // loader thread mapping: 1024 16B-chunks per tile; this thread does 4 (A) + 4 (W)
    const int lr = tid >> 1;                 // 0..127 (row for it-th chunk pair? no)
    (void)lr;

    auto issue = [&](int chunk, int st) {
        const int kc = chunk * 32;
        float* as = Asm[st];
        float* ws = Wsm[st];
#pragma unroll
        for (int it = 0; it < 4; it++) {
            const int idx = it * 256 + tid;
            const int r   = idx >> 3;        // 0..127
            const int c   = idx & 7;         // 16B chunk within 32 floats
            const int kk  = kc + c * 4;
            // A
            const int grow = row0 + r;
            const bool ok  = (grow < nrows);
            const int crow = ok ? grow : 0;
            const float* ap;
            if (SPLIT) {
                ap = (kk < 128) ? &A[(size_t)crow * 128 + kk]
                                : &A2[(size_t)crow * 128 + (kk - 128)];
            } else {
                ap = &A[(size_t)crow * IN + kk];
            }
            cp16(as + r * SST + c * 4, ap, ok ? 16 : 0);
            // W
            cp16(ws + r * SST + c * 4, &W[(size_t)(col0 + r) * IN + kk], 16);
        }
        cp_commit();
    };

    auto compute = [&](int st) {
        const float* as = Asm[st];
        const float* ws = Wsm[st];
#pragma unroll
        for (int ks = 0; ks < 4; ks++) {
            const int kp = ks * 8 + 2 * t;
            unsigned a[2][4];
#pragma unroll
            for (int fm = 0; fm < 2; fm++) {
                const int rb = warp_m * 32 + fm * 16;
                const uint2 p0 = *(const uint2*)(as + (rb + g) * SST + kp);
                const uint2 p1 = *(const uint2*)(as + (rb + g + 8) * SST + kp);
                a[fm][0] = p0.x; a[fm][1] = p1.x;
                a[fm][2] = p0.y; a[fm][3] = p1.y;
            }
#pragma unroll
            for (int nf = 0; nf < 8; nf++) {
                const uint2 bb = *(const uint2*)(ws + (colb + nf * 8 + g) * SST + kp);
                mma_tf32(acc[0][nf], a[0], bb.x, bb.y);
                mma_tf32(acc[1][nf], a[1], bb.x, bb.y);
            }
        }
    };

    issue(0, 0);
#pragma unroll 1
    for (int ch = 0; ch < NCH; ch++) {
        if (ch + 1 < NCH) {
            issue(ch + 1, (ch + 1) & 1);
            cp_wait1();
        } else {
            cp_wait0();
        }
        __syncthreads();
        compute(ch & 1);
        __syncthreads();
    }

    // ---------------- epilogue ----------------
    float2 bias2[8];
#pragma unroll
    for (int nf = 0; nf < 8; nf++)
        bias2[nf] = *(const float2*)&bias[col0 + colb + nf * 8 + 2 * t];

#pragma unroll
    for (int fm = 0; fm < 2; fm++) {
#pragma unroll
        for (int ro = 0; ro < 2; ro++) {
            const int row  = warp_m * 32 + fm * 16 + ro * 8 + g;
            const int grow = row0 + row;
            const bool ok  = (grow < nrows);
            float s = 0.f, s2 = 0.f;
#pragma unroll
            for (int nf = 0; nf < 8; nf++) {
                float v0 = acc[fm][nf][ro * 2 + 0] + bias2[nf].x;
                float v1 = acc[fm][nf][ro * 2 + 1] + bias2[nf].y;
                if (RELU) { v0 = fmaxf(v0, 0.f); v1 = fmaxf(v1, 0.f); }
                if (RES && ok) {
                    const float2 rv = *(const float2*)
                        &res[(size_t)grow * OUT + col0 + colb + nf * 8 + 2 * t];
                    v0 += rv.x; v1 += rv.y;
                }
                acc[fm][nf][ro * 2 + 0] = v0;
                acc[fm][nf][ro * 2 + 1] = v1;
                if (LN) { s += v0 + v1; s2 += v0 * v0 + v1 * v1; }
            }
            if (LN) {
                s  += __shfl_xor_sync(0xffffffffu, s, 1);
                s2 += __shfl_xor_sync(0xffffffffu, s2, 1);
                s  += __shfl_xor_sync(0xffffffffu, s, 2);
                s2 += __shfl_xor_sync(0xffffffffu, s2, 2);
                if (t == 0) lnp[warp_n * 128 + row] = make_float2(s, s2);
            }
        }
    }
    if (LN) __syncthreads();

#pragma unroll
    for (int fm = 0; fm < 2; fm++) {
#pragma unroll
        for (int ro = 0; ro < 2; ro++) {
            const int row  = warp_m * 32 + fm * 16 + ro * 8 + g;
            const int grow = row0 + row;
            if (grow >= nrows) continue;
            float mean = 0.f, rstd = 1.f;
            if (LN) {
                const float2 p0 = lnp[row];
                const float2 p1 = lnp[128 + row];
                const float s  = p0.x + p1.x;
                const float s2 = p0.y + p1.y;
                mean = s * (1.f / 128.f);
                const float var = s2 * (1.f / 128.f) - mean * mean;
                rstd = rsqrtf(var + 1e-5f);
            }
#pragma unroll
            for (int nf = 0; nf < 8; nf++) {
                const int col = col0 + colb + nf * 8 + 2 * t;
                float v0 = acc[fm][nf][ro * 2 + 0];
                float v1 = acc[fm][nf][ro * 2 + 1];
                if (LN) {
                    const float2 gv = *(const float2*)&lng[col];
                    const float2 bb = *(const float2*)&lnb[col];
                    v0 = (v0 - mean) * rstd * gv.x + bb.x;
                    v1 = (v1 - mean) * rstd * gv.y + bb.y;
                }
                if (OMODE == 1) {
                    *(float2*)&C[(size_t)grow * OUT + col] =
                        make_float2(tf32r(v0), tf32r(v1));
                } else {
                    // final: inverse-permute to logical columns, scalar stores
                    const int l0 = (col & ~7) + ((col & 1) << 2) + ((col & 7) >> 1);
                    const int c1 = col + 1;
                    const int l1 = (c1 & ~7) + ((c1 & 1) << 2) + ((c1 & 7) >> 1);
                    C[(size_t)grow * OUT + l0] = v0;
                    C[(size_t)grow * OUT + l1] = v1;
                }
            }
        }
    }
}

// ---------------- attention: warp per node (permuted world) ----------------
__global__ __launch_bounds__(256) void attn_kernel(
    const float* __restrict__ qkv, const int* __restrict__ samp,
    float* __restrict__ out, int n)
{
    const int warp = (blockIdx.x * blockDim.x + threadIdx.x) >> 5;
    const int lane = threadIdx.x & 31;
    if (warp >= n) return;
    const int node = warp;
    const int c0 = lane * 4;

    const float4 q = *(const float4*)&qkv[node * 384 + c0];
    int idxs[KATT];
#pragma unroll
    for (int j = 0; j < KATT; j++) idxs[j] = samp[node * KATT + j];

    const float scale = 0.17677669529663687f;   // 1/sqrt(32)
    float s[KATT];
    float mx = -1e30f;
#pragma unroll
    for (int j = 0; j < KATT; j++) {
        const float4 kv = *(const float4*)&qkv[idxs[j] * 384 + 128 + c0];
        float d = q.x * kv.x + q.y * kv.y + q.z * kv.z + q.w * kv.w;
        d += __shfl_xor_sync(0xffffffffu, d, 1);
        d += __shfl_xor_sync(0xffffffffu, d, 2);
        d += __shfl_xor_sync(0xffffffffu, d, 4);
        s[j] = d * scale;
        mx = fmaxf(mx, s[j]);
    }
    float sum = 0.f;
#pragma unroll
    for (int j = 0; j < KATT; j++) { s[j] = expf(s[j] - mx); sum += s[j]; }
    const float inv = 1.f / sum;

    float4 a = make_float4(0.f, 0.f, 0.f, 0.f);
#pragma unroll
    for (int j = 0; j < KATT; j++) {
        const float4 vv = *(const float4*)&qkv[idxs[j] * 384 + 256 + c0];
        const float w = s[j] * inv;
        a.x += w * vv.x; a.y += w * vv.y;
        a.z += w * vv.z; a.w += w * vv.w;
    }
    *(float4*)&out[node * 128 + c0] =
        make_float4(tf32r(a.x), tf32r(a.y), tf32r(a.z), tf32r(a.w));
}

// ---------------- GNN CSR build + aggregate ----------------
__global__ void hist_kernel(const int* __restrict__ src, int* __restrict__ deg, int e) {
    const int i = blockIdx.x * blockDim.x + threadIdx.x;
    if (i < e) atomicAdd(&deg[src[i]], 1);
}

__global__ void scan_kernel(const int* __restrict__ deg, int* __restrict__ off, int n) {
    __shared__ int sh[32];
    __shared__ int carry_s;
    const int tid = threadIdx.x;
    const int lane = tid & 31, wid = tid >> 5;
    if (tid == 0) carry_s = 0;
    __syncthreads();
    for (int base = 0; base < n; base += 1024) {
        const int i = base + tid;
        const int v = (i < n) ? deg[i] : 0;
        int x = v;
#pragma unroll
        for (int d = 1; d < 32; d <<= 1) {
            const int t = __shfl_up_sync(0xffffffffu, x, d);
            if (lane >= d) x += t;
        }
        if (lane == 31) sh[wid] = x;
        __syncthreads();
        if (wid == 0) {
            int w = sh[lane];
#pragma unroll
            for (int d = 1; d < 32; d <<= 1) {
                const int t = __shfl_up_sync(0xffffffffu, w, d);
                if (lane >= d) w += t;
            }
            sh[lane] = w;
        }
        __syncthreads();
        const int incl = x + (wid > 0 ? sh[wid - 1] : 0) + carry_s;
        if (i < n) off[i] = incl - v;   // exclusive
        __syncthreads();
        if (tid == 1023) carry_s = incl;
        __syncthreads();
    }
    if (tid == 0) off[n] = carry_s;
}

__global__ void scatter_kernel(const int* __restrict__ src, const int* __restrict__ dst,
                               const int* __restrict__ off, int* __restrict__ cnt,
                               int* __restrict__ csr, int e) {
    const int i = blockIdx.x * blockDim.x + threadIdx.x;
    if (i < e) {
        const int s = src[i];
        const int pos = off[s] + atomicAdd(&cnt[s], 1);
        csr[pos] = dst[i];
    }
}

__global__ __launch_bounds__(256) void agg_kernel(
    const float* __restrict__ h, const int* __restrict__ off,
    const int* __restrict__ csr, float* __restrict__ neigh, int n)
{
    const int warp = (blockIdx.x * blockDim.x + threadIdx.x) >> 5;
    const int lane = threadIdx.x & 31;
    if (warp >= n) return;
    const int beg = off[warp], end = off[warp + 1];
    float4 acc = make_float4(0.f, 0.f, 0.f, 0.f);
    for (int e = beg; e < end; e++) {
        const int d = csr[e];
        const float4 hv = *(const float4*)&h[d * 128 + lane * 4];
        acc.x += hv.x; acc.y += hv.y; acc.z += hv.z; acc.w += hv.w;
    }
    *(float4*)&neigh[warp * 128 + lane * 4] =
        make_float4(tf32r(acc.x), tf32r(acc.y), tf32r(acc.z), tf32r(acc.w));
}

// ---------------- host orchestration ----------------
extern "C" void kernel_launch(void* const* d_in, const int* in_sizes, int n_in,
                              void* d_out, int out_size)
{
    const float* x       = (const float*)d_in[0];
    const int*   samples = (const int*)d_in[1];
    const int*   esrc    = (const int*)d_in[2];
    const int*   edst    = (const int*)d_in[3];
    const float* t_in_w  = (const float*)d_in[4];
    const float* t_in_b  = (const float*)d_in[5];
    const float* t_out_w = (const float*)d_in[6];
    const float* t_out_b = (const float*)d_in[7];
    const float* t_f_w1  = (const float*)d_in[8];
    const float* t_f_b1  = (const float*)d_in[9];
    const float* t_f_w2  = (const float*)d_in[10];
    const float* t_f_b2  = (const float*)d_in[11];
    const float* ln1g    = (const float*)d_in[12];
    const float* ln1b    = (const float*)d_in[13];
    const float* ln2g    = (const float*)d_in[14];
    const float* ln2b    = (const float*)d_in[15];
    const float* gw      = (const float*)d_in[16];
    const float* gb      = (const float*)d_in[17];
    const float* glng    = (const float*)d_in[18];
    const float* glnb    = (const float*)d_in[19];

    float *pqkv, *pattn, *pa, *ptmp, *ph, *ph2, *pneigh, *phx;
    int *pdeg, *poff, *pcnt, *pcsr;
    float *wqkv, *wout, *wf1, *wf2, *wg;
    float *bqkv, *bout, *bf1, *bf2, *l1g, *l1b, *l2g, *l2b, *bg, *gg, *gbv;
    cudaGetSymbolAddress((void**)&pqkv,   g_qkv);
    cudaGetSymbolAddress((void**)&pattn,  g_attn);
    cudaGetSymbolAddress((void**)&pa,     g_a);
    cudaGetSymbolAddress((void**)&ptmp,   g_tmp);
    cudaGetSymbolAddress((void**)&ph,     g_h);
    cudaGetSymbolAddress((void**)&ph2,    g_h2);
    cudaGetSymbolAddress((void**)&pneigh, g_neigh);
    cudaGetSymbolAddress((void**)&phx,    g_hx);
    cudaGetSymbolAddress((void**)&pdeg,   g_deg);
    cudaGetSymbolAddress((void**)&poff,   g_off);
    cudaGetSymbolAddress((void**)&pcnt,   g_cnt);
    cudaGetSymbolAddress((void**)&pcsr,   g_csr);
    cudaGetSymbolAddress((void**)&wqkv,   g_wqkv);
    cudaGetSymbolAddress((void**)&wout,   g_wout);
    cudaGetSymbolAddress((void**)&wf1,    g_wf1);
    cudaGetSymbolAddress((void**)&wf2,    g_wf2);
    cudaGetSymbolAddress((void**)&wg,     g_wg);
    cudaGetSymbolAddress((void**)&bqkv,   g_bqkv);
    cudaGetSymbolAddress((void**)&bout,   g_bout);
    cudaGetSymbolAddress((void**)&bf1,    g_bf1);
    cudaGetSymbolAddress((void**)&bf2,    g_bf2);
    cudaGetSymbolAddress((void**)&l1g,    g_l1g);
    cudaGetSymbolAddress((void**)&l1b,    g_l1b);
    cudaGetSymbolAddress((void**)&l2g,    g_l2g);
    cudaGetSymbolAddress((void**)&l2b,    g_l2b);
    cudaGetSymbolAddress((void**)&bg,     g_bg);
    cudaGetSymbolAddress((void**)&gg,     g_gg);
    cudaGetSymbolAddress((void**)&gbv,    g_gb);

    const int n = NN;
    const int e = EE;
    const int GX = (n + 127) / 128;
    const int WARP_GRID = (n + 7) / 8;
    const int EG = (e + 255) / 256;
    const size_t SMEMSZ = (4 * 128 * 40) * sizeof(float) + 256 * sizeof(float2);

    // raise dynamic smem limits (host-side, idempotent)
    cudaFuncSetAttribute(gemm_tc<128, 384, false, false, false, false, 1>,
                         cudaFuncAttributeMaxDynamicSharedMemorySize, (int)SMEMSZ);
    cudaFuncSetAttribute(gemm_tc<128, 128, false, true, true, false, 1>,
                         cudaFuncAttributeMaxDynamicSharedMemorySize, (int)SMEMSZ);
    cudaFuncSetAttribute(gemm_tc<128, 512, true, false, false, false, 1>,
                         cudaFuncAttributeMaxDynamicSharedMemorySize, (int)SMEMSZ);
    cudaFuncSetAttribute(gemm_tc<512, 128, false, true, true, false, 1>,
                         cudaFuncAttributeMaxDynamicSharedMemorySize, (int)SMEMSZ);
    cudaFuncSetAttribute(gemm_tc<512, 128, false, true, true, false, 2>,
                         cudaFuncAttributeMaxDynamicSharedMemorySize, (int)SMEMSZ);
    cudaFuncSetAttribute(gemm_tc<256, 128, true, true, true, true, 1>,
                         cudaFuncAttributeMaxDynamicSharedMemorySize, (int)SMEMSZ);

    // ---- parameter conversion table ----
    PTab tab;
    int ne = 0;
    for (int i = 0; i < 3; i++) {
        tab.e[ne++] = { t_in_w  + (size_t)i * 384 * 128, wqkv + (size_t)i * 384 * 128, 384, 128, 0 };
        tab.e[ne++] = { t_out_w + (size_t)i * 128 * 128, wout + (size_t)i * 128 * 128, 128, 128, 0 };
        tab.e[ne++] = { t_f_w1  + (size_t)i * 512 * 128, wf1  + (size_t)i * 512 * 128, 512, 128, 0 };
        tab.e[ne++] = { t_f_w2  + (size_t)i * 128 * 512, wf2  + (size_t)i * 128 * 512, 128, 512, 0 };
        tab.e[ne++] = { t_in_b  + i * 384, bqkv + i * 384, 1, 384, 1 };
        tab.e[ne++] = { t_out_b + i * 128, bout + i * 128, 1, 128, 1 };
        tab.e[ne++] = { t_f_b1  + i * 512, bf1  + i * 512, 1, 512, 1 };
        tab.e[ne++] = { t_f_b2  + i * 128, bf2  + i * 128, 1, 128, 1 };
        tab.e[ne++] = { ln1g + i * 128, l1g + i * 128, 1, 128, 1 };
        tab.e[ne++] = { ln1b + i * 128, l1b + i * 128, 1, 128, 1 };
        tab.e[ne++] = { ln2g + i * 128, l2g + i * 128, 1, 128, 1 };
        tab.e[ne++] = { ln2b + i * 128, l2b + i * 128, 1, 128, 1 };
    }
    for (int i = 0; i < 2; i++) {
        tab.e[ne++] = { gw + (size_t)i * 128 * 256, wg + (size_t)i * 128 * 256, 128, 256, 0 };
        tab.e[ne++] = { gb   + i * 128, bg  + i * 128, 1, 128, 1 };
        tab.e[ne++] = { glng + i * 128, gg  + i * 128, 1, 128, 1 };
        tab.e[ne++] = { glnb + i * 128, gbv + i * 128, 1, 128, 1 };
    }
    param_conv<<<dim3(64, ne), 256>>>(tab, ne);
    conv_x<<<(NN * 128 + 255) / 256, 256>>>(x, phx);

    // ---- build CSR once (reused by both GNN layers) ----
    cudaMemsetAsync(pdeg, 0, n * sizeof(int));
    cudaMemsetAsync(pcnt, 0, n * sizeof(int));
    hist_kernel<<<EG, 256>>>(esrc, pdeg, e);
    scan_kernel<<<1, 1024>>>(pdeg, poff, n);
    scatter_kernel<<<EG, 256>>>(esrc, edst, poff, pcnt, pcsr, e);

    // ---- transformer layer ----
    auto run_trans = [&](const float* hin, float* hout, int i, bool final_layer) {
        gemm_tc<128, 384, false, false, false, false, 1><<<dim3(GX, 3), 256, SMEMSZ>>>(
            hin, nullptr, wqkv + (size_t)i * 384 * 128, bqkv + i * 384,
            nullptr, nullptr, nullptr, pqkv, n);
        attn_kernel<<<WARP_GRID, 256>>>(pqkv, samples, pattn, n);
        gemm_tc<128, 128, false, true, true, false, 1><<<dim3(GX, 1), 256, SMEMSZ>>>(
            pattn, nullptr, wout + (size_t)i * 128 * 128, bout + i * 128,
            hin, l1g + i * 128, l1b + i * 128, pa, n);
        gemm_tc<128, 512, true, false, false, false, 1><<<dim3(GX, 4), 256, SMEMSZ>>>(
            pa, nullptr, wf1 + (size_t)i * 512 * 128, bf1 + i * 512,
            nullptr, nullptr, nullptr, ptmp, n);
        if (final_layer) {
            gemm_tc<512, 128, false, true, true, false, 2><<<dim3(GX, 1), 256, SMEMSZ>>>(
                ptmp, nullptr, wf2 + (size_t)i * 128 * 512, bf2 + i * 128,
                pa, l2g + i * 128, l2b + i * 128, hout, n);
        } else {
            gemm_tc<512, 128, false, true, true, false, 1><<<dim3(GX, 1), 256, SMEMSZ>>>(
                ptmp, nullptr, wf2 + (size_t)i * 128 * 512, bf2 + i * 128,
                pa, l2g + i * 128, l2b + i * 128, hout, n);
        }
    };

    // ---- GNN layer ----
    auto run_gnn = [&](const float* hin, float* hout, int i) {
        agg_kernel<<<WARP_GRID, 256>>>(hin, poff, pcsr, pneigh, n);
        gemm_tc<256, 128, true, true, true, true, 1><<<dim3(GX, 1), 256, SMEMSZ>>>(
            hin, pneigh, wg + (size_t)i * 128 * 256, bg + i * 128,
            hin, gg + i * 128, gbv + i * 128, hout, n);
    };

    run_trans(phx, ph, 0, false);
    run_gnn(ph, ph2, 0);
    run_trans(ph2, ph, 1, false);
    run_gnn(ph, ph2, 1);
    run_trans(ph2, (float*)d_out, 2, true);
}

// round 4
// speedup vs baseline: 1.9488x; 1.0227x over previous
#include <cuda_runtime.h>

#define NN 50000
#define DD 128
#define EE 1600000
#define KATT 20
#define SCAN_TILE 4096
#define SCAN_BLOCKS ((NN + SCAN_TILE - 1) / SCAN_TILE)

// ---------------- scratch (static device allocations) ----------------
__device__ float g_qkv[NN * 384];
__device__ float g_attn[NN * DD];
__device__ float g_a[NN * DD];
__device__ float g_tmp[NN * 512];
__device__ float g_h[NN * DD];
__device__ float g_h2[NN * DD];
__device__ float g_neigh[NN * DD];
__device__ float g_hx[NN * DD];
__device__ int   g_deg[NN];
__device__ int   g_off[NN + 1];
__device__ int   g_cnt[NN];
__device__ int   g_csr[EE];
__device__ int   g_bsum[SCAN_BLOCKS];

// converted (tf32-rounded, permuted) parameters
__device__ float g_wqkv[3 * 384 * 128];
__device__ float g_wout[3 * 128 * 128];
__device__ float g_wf1 [3 * 512 * 128];
__device__ float g_wf2 [3 * 128 * 512];
__device__ float g_wg  [2 * 128 * 256];
__device__ float g_bqkv[3 * 384];
__device__ float g_bout[3 * 128];
__device__ float g_bf1 [3 * 512];
__device__ float g_bf2 [3 * 128];
__device__ float g_l1g [3 * 128];
__device__ float g_l1b [3 * 128];
__device__ float g_l2g [3 * 128];
__device__ float g_l2b [3 * 128];
__device__ float g_bg  [2 * 128];
__device__ float g_gg  [2 * 128];
__device__ float g_gb  [2 * 128];

// ---------------- helpers ----------------
__device__ __forceinline__ unsigned tf32cvt(float x) {
    unsigned r;
    asm("cvt.rna.tf32.f32 %0, %1;" : "=r"(r) : "f"(x));
    return r;
}
__device__ __forceinline__ float tf32r(float x) { return __uint_as_float(tf32cvt(x)); }

// within-8 column permutation for mma k-fragments (logical -> physical)
__device__ __forceinline__ int gperm(int i) {
    return (i & ~7) + ((i & 3) << 1) + ((i & 4) >> 2);
}

__device__ __forceinline__ void mma_tf32(float c[4], const unsigned a[4],
                                         unsigned b0, unsigned b1) {
    asm("mma.sync.aligned.m16n8k8.row.col.f32.tf32.tf32.f32 "
        "{%0,%1,%2,%3}, {%4,%5,%6,%7}, {%8,%9}, {%0,%1,%2,%3};\n"
        : "+f"(c[0]), "+f"(c[1]), "+f"(c[2]), "+f"(c[3])
        : "r"(a[0]), "r"(a[1]), "r"(a[2]), "r"(a[3]), "r"(b0), "r"(b1));
}

__device__ __forceinline__ void cp16(void* sdst, const void* gsrc, int sz) {
    unsigned s = (unsigned)__cvta_generic_to_shared(sdst);
    asm volatile("cp.async.cg.shared.global [%0], [%1], 16, %2;\n"
                 :: "r"(s), "l"(gsrc), "r"(sz));
}
__device__ __forceinline__ void cp_commit() {
    asm volatile("cp.async.commit_group;\n");
}
__device__ __forceinline__ void cp_wait1() {
    asm volatile("cp.async.wait_group 1;\n");
}
__device__ __forceinline__ void cp_wait0() {
    asm volatile("cp.async.wait_group 0;\n");
}

// ---------------- parameter conversion ----------------
struct PEnt { const float* s; float* d; int rows; int cols; int mode; };
struct PTab { PEnt e[48]; };

__global__ void param_conv(PTab t, int n) {
    const int ei = blockIdx.y;
    if (ei >= n) return;
    const PEnt en = t.e[ei];
    const int total = en.rows * en.cols;
    for (int i = blockIdx.x * blockDim.x + threadIdx.x; i < total;
         i += gridDim.x * blockDim.x) {
        if (en.mode == 0) {           // matrix: permute both dims + tf32 round
            const int r = i / en.cols, c = i % en.cols;
            en.d[(size_t)gperm(r) * en.cols + gperm(c)] = tf32r(en.s[i]);
        } else {                      // vector: permute only
            en.d[gperm(i)] = en.s[i];
        }
    }
}

__global__ void conv_x(const float* __restrict__ x, float* __restrict__ o) {
    const int i = blockIdx.x * blockDim.x + threadIdx.x;
    if (i < NN * 128) {
        const int r = i >> 7, c = i & 127;
        o[(r << 7) + gperm(c)] = tf32r(x[i]);
    }
}

// ---------------- fused TF32 tensor-core GEMM (cp.async pipelined) ----------------
// All operands live in "permuted world" (within-8 col permutation) and are
// pre-rounded to tf32, so smem tiles are raw byte copies of gmem.
// Block 128x128, 8 warps (4m x 2n), warp tile 32x64, BK=32, 2-stage cp.async.
// OMODE: 1 = store tf32-rounded (activation), 2 = final store (inverse-permute cols).
template <int IN, int OUT, bool RELU, bool RES, bool LN, bool SPLIT, int OMODE>
__global__ __launch_bounds__(256, 2) void gemm_tc(
    const float* __restrict__ A, const float* __restrict__ A2,
    const float* __restrict__ W, const float* __restrict__ bias,
    const float* __restrict__ res,
    const float* __restrict__ lng, const float* __restrict__ lnb,
    float* __restrict__ C, int nrows)
{
    constexpr int SST = 40;                      // smem row stride (floats)
    extern __shared__ float smem[];
    float* Asm[2] = { smem,             smem + 128 * SST };
    float* Wsm[2] = { smem + 2 * 128 * SST, smem + 3 * 128 * SST };
    float2* lnp   = (float2*)(smem + 4 * 128 * SST);   // [2][128]

    const int tid    = threadIdx.x;
    const int lane   = tid & 31;
    const int warp   = tid >> 5;
    const int warp_m = warp & 3;
    const int warp_n = warp >> 2;
    const int g      = lane >> 2;
    const int t      = lane & 3;
    const int row0   = blockIdx.x * 128;
    const int col0   = blockIdx.y * 128;
    const int colb   = warp_n * 64;

    float acc[2][8][4];
#pragma unroll
    for (int fm = 0; fm < 2; fm++)
#pragma unroll
        for (int nf = 0; nf < 8; nf++)
#pragma unroll
            for (int r = 0; r < 4; r++) acc[fm][nf][r] = 0.f;

    constexpr int NCH = IN / 32;

    auto issue = [&](int chunk, int st) {
        const int kc = chunk * 32;
        float* as = Asm[st];
        float* ws = Wsm[st];
#pragma unroll
        for (int it = 0; it < 4; it++) {
            const int idx = it * 256 + tid;
            const int r   = idx >> 3;        // 0..127
            const int c   = idx & 7;         // 16B chunk within 32 floats
            const int kk  = kc + c * 4;
            const int grow = row0 + r;
            const bool ok  = (grow < nrows);
            const int crow = ok ? grow : 0;
            const float* ap;
            if (SPLIT) {
                ap = (kk < 128) ? &A[(size_t)crow * 128 + kk]
                                : &A2[(size_t)crow * 128 + (kk - 128)];
            } else {
                ap = &A[(size_t)crow * IN + kk];
            }
            cp16(as + r * SST + c * 4, ap, ok ? 16 : 0);
            cp16(ws + r * SST + c * 4, &W[(size_t)(col0 + r) * IN + kk], 16);
        }
        cp_commit();
    };

    auto compute = [&](int st) {
        const float* as = Asm[st];
        const float* ws = Wsm[st];
#pragma unroll
        for (int ks = 0; ks < 4; ks++) {
            const int kp = ks * 8 + 2 * t;
            unsigned a[2][4];
#pragma unroll
            for (int fm = 0; fm < 2; fm++) {
                const int rb = warp_m * 32 + fm * 16;
                const uint2 p0 = *(const uint2*)(as + (rb + g) * SST + kp);
                const uint2 p1 = *(const uint2*)(as + (rb + g + 8) * SST + kp);
                a[fm][0] = p0.x; a[fm][1] = p1.x;
                a[fm][2] = p0.y; a[fm][3] = p1.y;
            }
#pragma unroll
            for (int nf = 0; nf < 8; nf++) {
                const uint2 bb = *(const uint2*)(ws + (colb + nf * 8 + g) * SST + kp);
                mma_tf32(acc[0][nf], a[0], bb.x, bb.y);
                mma_tf32(acc[1][nf], a[1], bb.x, bb.y);
            }
        }
    };

    issue(0, 0);
#pragma unroll 1
    for (int ch = 0; ch < NCH; ch++) {
        if (ch + 1 < NCH) {
            issue(ch + 1, (ch + 1) & 1);
            cp_wait1();
        } else {
            cp_wait0();
        }
        __syncthreads();
        compute(ch & 1);
        __syncthreads();
    }

    // ---------------- epilogue ----------------
    float2 bias2[8];
#pragma unroll
    for (int nf = 0; nf < 8; nf++)
        bias2[nf] = *(const float2*)&bias[col0 + colb + nf * 8 + 2 * t];

#pragma unroll
    for (int fm = 0; fm < 2; fm++) {
#pragma unroll
        for (int ro = 0; ro < 2; ro++) {
            const int row  = warp_m * 32 + fm * 16 + ro * 8 + g;
            const int grow = row0 + row;
            const bool ok  = (grow < nrows);
            float s = 0.f, s2 = 0.f;
#pragma unroll
            for (int nf = 0; nf < 8; nf++) {
                float v0 = acc[fm][nf][ro * 2 + 0] + bias2[nf].x;
                float v1 = acc[fm][nf][ro * 2 + 1] + bias2[nf].y;
                if (RELU) { v0 = fmaxf(v0, 0.f); v1 = fmaxf(v1, 0.f); }
                if (RES && ok) {
                    const float2 rv = *(const float2*)
                        &res[(size_t)grow * OUT + col0 + colb + nf * 8 + 2 * t];
                    v0 += rv.x; v1 += rv.y;
                }
                acc[fm][nf][ro * 2 + 0] = v0;
                acc[fm][nf][ro * 2 + 1] = v1;
                if (LN) { s += v0 + v1; s2 += v0 * v0 + v1 * v1; }
            }
            if (LN) {
                s  += __shfl_xor_sync(0xffffffffu, s, 1);
                s2 += __shfl_xor_sync(0xffffffffu, s2, 1);
                s  += __shfl_xor_sync(0xffffffffu, s, 2);
                s2 += __shfl_xor_sync(0xffffffffu, s2, 2);
                if (t == 0) lnp[warp_n * 128 + row] = make_float2(s, s2);
            }
        }
    }
    if (LN) __syncthreads();

#pragma unroll
    for (int fm = 0; fm < 2; fm++) {
#pragma unroll
        for (int ro = 0; ro < 2; ro++) {
            const int row  = warp_m * 32 + fm * 16 + ro * 8 + g;
            const int grow = row0 + row;
            if (grow >= nrows) continue;
            float mean = 0.f, rstd = 1.f;
            if (LN) {
                const float2 p0 = lnp[row];
                const float2 p1 = lnp[128 + row];
                const float s  = p0.x + p1.x;
                const float s2 = p0.y + p1.y;
                mean = s * (1.f / 128.f);
                const float var = s2 * (1.f / 128.f) - mean * mean;
                rstd = rsqrtf(var + 1e-5f);
            }
#pragma unroll
            for (int nf = 0; nf < 8; nf++) {
                const int col = col0 + colb + nf * 8 + 2 * t;
                float v0 = acc[fm][nf][ro * 2 + 0];
                float v1 = acc[fm][nf][ro * 2 + 1];
                if (LN) {
                    const float2 gv = *(const float2*)&lng[col];
                    const float2 bb = *(const float2*)&lnb[col];
                    v0 = (v0 - mean) * rstd * gv.x + bb.x;
                    v1 = (v1 - mean) * rstd * gv.y + bb.y;
                }
                if (OMODE == 1) {
                    *(float2*)&C[(size_t)grow * OUT + col] =
                        make_float2(tf32r(v0), tf32r(v1));
                } else {
                    const int l0 = (col & ~7) + ((col & 1) << 2) + ((col & 7) >> 1);
                    const int c1 = col + 1;
                    const int l1 = (c1 & ~7) + ((c1 & 1) << 2) + ((c1 & 7) >> 1);
                    C[(size_t)grow * OUT + l0] = v0;
                    C[(size_t)grow * OUT + l1] = v1;
                }
            }
        }
    }
}

// ---------------- attention: warp per node (permuted world) ----------------
__global__ __launch_bounds__(256) void attn_kernel(
    const float* __restrict__ qkv, const int* __restrict__ samp,
    float* __restrict__ out, int n)
{
    const int warp = (blockIdx.x * blockDim.x + threadIdx.x) >> 5;
    const int lane = threadIdx.x & 31;
    if (warp >= n) return;
    const int node = warp;
    const int c0 = lane * 4;

    const float4 q = *(const float4*)&qkv[node * 384 + c0];
    int idxs[KATT];
#pragma unroll
    for (int j = 0; j < KATT; j++) idxs[j] = samp[node * KATT + j];

    const float scale = 0.17677669529663687f;   // 1/sqrt(32)
    float s[KATT];
    float mx = -1e30f;
#pragma unroll
    for (int j = 0; j < KATT; j++) {
        const float4 kv = *(const float4*)&qkv[idxs[j] * 384 + 128 + c0];
        float d = q.x * kv.x + q.y * kv.y + q.z * kv.z + q.w * kv.w;
        d += __shfl_xor_sync(0xffffffffu, d, 1);
        d += __shfl_xor_sync(0xffffffffu, d, 2);
        d += __shfl_xor_sync(0xffffffffu, d, 4);
        s[j] = d * scale;
        mx = fmaxf(mx, s[j]);
    }
    float sum = 0.f;
#pragma unroll
    for (int j = 0; j < KATT; j++) { s[j] = __expf(s[j] - mx); sum += s[j]; }
    const float inv = 1.f / sum;

    float4 a = make_float4(0.f, 0.f, 0.f, 0.f);
#pragma unroll
    for (int j = 0; j < KATT; j++) {
        const float4 vv = *(const float4*)&qkv[idxs[j] * 384 + 256 + c0];
        const float w = s[j] * inv;
        a.x += w * vv.x; a.y += w * vv.y;
        a.z += w * vv.z; a.w += w * vv.w;
    }
    *(float4*)&out[node * 128 + c0] =
        make_float4(tf32r(a.x), tf32r(a.y), tf32r(a.z), tf32r(a.w));
}

// ---------------- GNN CSR build + aggregate ----------------
__global__ void zero_kernel(int* __restrict__ a, int* __restrict__ b, int n) {
    const int i = blockIdx.x * blockDim.x + threadIdx.x;
    if (i < n) { a[i] = 0; b[i] = 0; }
}

__global__ void hist_kernel(const int* __restrict__ src, int* __restrict__ deg, int e) {
    const int i = blockIdx.x * blockDim.x + threadIdx.x;
    if (i < e) atomicAdd(&deg[src[i]], 1);
}

// scan stage 1: per-block exclusive scan (tile = 4096), write block totals
__global__ __launch_bounds__(256) void scan1_kernel(
    const int* __restrict__ deg, int* __restrict__ off, int* __restrict__ bsum, int n)
{
    __shared__ int wsum[8];
    const int tid  = threadIdx.x;
    const int lane = tid & 31, wid = tid >> 5;
    const int base = blockIdx.x * SCAN_TILE + tid * 16;

    int v[16];
    int tsum = 0;
#pragma unroll
    for (int i = 0; i < 16; i++) {
        const int gi = base + i;
        v[i] = (gi < n) ? deg[gi] : 0;
        tsum += v[i];
    }
    // warp-exclusive scan of per-thread sums
    int x = tsum;
#pragma unroll
    for (int d = 1; d < 32; d <<= 1) {
        const int t = __shfl_up_sync(0xffffffffu, x, d);
        if (lane >= d) x += t;
    }
    if (lane == 31) wsum[wid] = x;
    __syncthreads();
    int wpre = 0;
#pragma unroll
    for (int w = 0; w < 8; w++) wpre += (w < wid) ? wsum[w] : 0;
    int run = wpre + x - tsum;     // exclusive prefix for this thread
#pragma unroll
    for (int i = 0; i < 16; i++) {
        const int gi = base + i;
        if (gi < n) off[gi] = run;
        run += v[i];
    }
    if (tid == 255) bsum[blockIdx.x] = wpre + x;   // block total
}

// scan stage 2: add cross-block prefix (redundant tiny reduction per block)
__global__ __launch_bounds__(256) void scan2_kernel(
    const int* __restrict__ bsum, int* __restrict__ off, int n)
{
    __shared__ int pre_s, tot_s;
    if (threadIdx.x == 0) {
        int p = 0, t = 0;
#pragma unroll
        for (int b = 0; b < SCAN_BLOCKS; b++) {
            if (b < (int)blockIdx.x) p += bsum[b];
            t += bsum[b];
        }
        pre_s = p; tot_s = t;
    }
    __syncthreads();
    const int pre = pre_s;
    const int base = blockIdx.x * SCAN_TILE + threadIdx.x * 16;
#pragma unroll
    for (int i = 0; i < 16; i++) {
        const int gi = base + i;
        if (gi < n) off[gi] += pre;
    }
    if (blockIdx.x == 0 && threadIdx.x == 0) off[n] = tot_s;
}

__global__ void scatter_kernel(const int* __restrict__ src, const int* __restrict__ dst,
                               const int* __restrict__ off, int* __restrict__ cnt,
                               int* __restrict__ csr, int e) {
    const int i = blockIdx.x * blockDim.x + threadIdx.x;
    if (i < e) {
        const int s = src[i];
        const int pos = off[s] + atomicAdd(&cnt[s], 1);
        csr[pos] = dst[i];
    }
}

__global__ __launch_bounds__(256) void agg_kernel(
    const float* __restrict__ h, const int* __restrict__ off,
    const int* __restrict__ csr, float* __restrict__ neigh, int n)
{
    const int warp = (blockIdx.x * blockDim.x + threadIdx.x) >> 5;
    const int lane = threadIdx.x & 31;
    if (warp >= n) return;
    const int beg = off[warp], end = off[warp + 1];
    float4 acc0 = make_float4(0.f, 0.f, 0.f, 0.f);
    float4 acc1 = make_float4(0.f, 0.f, 0.f, 0.f);
    int e = beg;
    for (; e + 2 <= end; e += 2) {
        const int d0 = csr[e];
        const int d1 = csr[e + 1];
        const float4 h0 = *(const float4*)&h[(size_t)d0 * 128 + lane * 4];
        const float4 h1 = *(const float4*)&h[(size_t)d1 * 128 + lane * 4];
        acc0.x += h0.x; acc0.y += h0.y; acc0.z += h0.z; acc0.w += h0.w;
        acc1.x += h1.x; acc1.y += h1.y; acc1.z += h1.z; acc1.w += h1.w;
    }
    if (e < end) {
        const int d0 = csr[e];
        const float4 h0 = *(const float4*)&h[(size_t)d0 * 128 + lane * 4];
        acc0.x += h0.x; acc0.y += h0.y; acc0.z += h0.z; acc0.w += h0.w;
    }
    acc0.x += acc1.x; acc0.y += acc1.y; acc0.z += acc1.z; acc0.w += acc1.w;
    *(float4*)&neigh[(size_t)warp * 128 + lane * 4] =
        make_float4(tf32r(acc0.x), tf32r(acc0.y), tf32r(acc0.z), tf32r(acc0.w));
}

// ---------------- host orchestration ----------------
extern "C" void kernel_launch(void* const* d_in, const int* in_sizes, int n_in,
                              void* d_out, int out_size)
{
    const float* x       = (const float*)d_in[0];
    const int*   samples = (const int*)d_in[1];
    const int*   esrc    = (const int*)d_in[2];
    const int*   edst    = (const int*)d_in[3];
    const float* t_in_w  = (const float*)d_in[4];
    const float* t_in_b  = (const float*)d_in[5];
    const float* t_out_w = (const float*)d_in[6];
    const float* t_out_b = (const float*)d_in[7];
    const float* t_f_w1  = (const float*)d_in[8];
    const float* t_f_b1  = (const float*)d_in[9];
    const float* t_f_w2  = (const float*)d_in[10];
    const float* t_f_b2  = (const float*)d_in[11];
    const float* ln1g    = (const float*)d_in[12];
    const float* ln1b    = (const float*)d_in[13];
    const float* ln2g    = (const float*)d_in[14];
    const float* ln2b    = (const float*)d_in[15];
    const float* gw      = (const float*)d_in[16];
    const float* gb      = (const float*)d_in[17];
    const float* glng    = (const float*)d_in[18];
    const float* glnb    = (const float*)d_in[19];

    float *pqkv, *pattn, *pa, *ptmp, *ph, *ph2, *pneigh, *phx;
    int *pdeg, *poff, *pcnt, *pcsr, *pbsum;
    float *wqkv, *wout, *wf1, *wf2, *wg;
    float *bqkv, *bout, *bf1, *bf2, *l1g, *l1b, *l2g, *l2b, *bg, *gg, *gbv;
    cudaGetSymbolAddress((void**)&pqkv,   g_qkv);
    cudaGetSymbolAddress((void**)&pattn,  g_attn);
    cudaGetSymbolAddress((void**)&pa,     g_a);
    cudaGetSymbolAddress((void**)&ptmp,   g_tmp);
    cudaGetSymbolAddress((void**)&ph,     g_h);
    cudaGetSymbolAddress((void**)&ph2,    g_h2);
    cudaGetSymbolAddress((void**)&pneigh, g_neigh);
    cudaGetSymbolAddress((void**)&phx,    g_hx);
    cudaGetSymbolAddress((void**)&pdeg,   g_deg);
    cudaGetSymbolAddress((void**)&poff,   g_off);
    cudaGetSymbolAddress((void**)&pcnt,   g_cnt);
    cudaGetSymbolAddress((void**)&pcsr,   g_csr);
    cudaGetSymbolAddress((void**)&pbsum,  g_bsum);
    cudaGetSymbolAddress((void**)&wqkv,   g_wqkv);
    cudaGetSymbolAddress((void**)&wout,   g_wout);
    cudaGetSymbolAddress((void**)&wf1,    g_wf1);
    cudaGetSymbolAddress((void**)&wf2,    g_wf2);
    cudaGetSymbolAddress((void**)&wg,     g_wg);
    cudaGetSymbolAddress((void**)&bqkv,   g_bqkv);
    cudaGetSymbolAddress((void**)&bout,   g_bout);
    cudaGetSymbolAddress((void**)&bf1,    g_bf1);
    cudaGetSymbolAddress((void**)&bf2,    g_bf2);
    cudaGetSymbolAddress((void**)&l1g,    g_l1g);
    cudaGetSymbolAddress((void**)&l1b,    g_l1b);
    cudaGetSymbolAddress((void**)&l2g,    g_l2g);
    cudaGetSymbolAddress((void**)&l2b,    g_l2b);
    cudaGetSymbolAddress((void**)&bg,     g_bg);
    cudaGetSymbolAddress((void**)&gg,     g_gg);
    cudaGetSymbolAddress((void**)&gbv,    g_gb);

    const int n = NN;
    const int e = EE;
    const int GX = (n + 127) / 128;
    const int WARP_GRID = (n + 7) / 8;
    const int EG = (e + 255) / 256;
    const size_t SMEMSZ = (4 * 128 * 40) * sizeof(float) + 256 * sizeof(float2);

    cudaFuncSetAttribute(gemm_tc<128, 384, false, false, false, false, 1>,
                         cudaFuncAttributeMaxDynamicSharedMemorySize, (int)SMEMSZ);
    cudaFuncSetAttribute(gemm_tc<128, 128, false, true, true, false, 1>,
                         cudaFuncAttributeMaxDynamicSharedMemorySize, (int)SMEMSZ);
    cudaFuncSetAttribute(gemm_tc<128, 512, true, false, false, false, 1>,
                         cudaFuncAttributeMaxDynamicSharedMemorySize, (int)SMEMSZ);
    cudaFuncSetAttribute(gemm_tc<512, 128, false, true, true, false, 1>,
                         cudaFuncAttributeMaxDynamicSharedMemorySize, (int)SMEMSZ);
    cudaFuncSetAttribute(gemm_tc<512, 128, false, true, true, false, 2>,
                         cudaFuncAttributeMaxDynamicSharedMemorySize, (int)SMEMSZ);
    cudaFuncSetAttribute(gemm_tc<256, 128, true, true, true, true, 1>,
                         cudaFuncAttributeMaxDynamicSharedMemorySize, (int)SMEMSZ);

    // ---- parameter conversion table ----
    PTab tab;
    int ne = 0;
    for (int i = 0; i < 3; i++) {
        tab.e[ne++] = { t_in_w  + (size_t)i * 384 * 128, wqkv + (size_t)i * 384 * 128, 384, 128, 0 };
        tab.e[ne++] = { t_out_w + (size_t)i * 128 * 128, wout + (size_t)i * 128 * 128, 128, 128, 0 };
        tab.e[ne++] = { t_f_w1  + (size_t)i * 512 * 128, wf1  + (size_t)i * 512 * 128, 512, 128, 0 };
        tab.e[ne++] = { t_f_w2  + (size_t)i * 128 * 512, wf2  + (size_t)i * 128 * 512, 128, 512, 0 };
        tab.e[ne++] = { t_in_b  + i * 384, bqkv + i * 384, 1, 384, 1 };
        tab.e[ne++] = { t_out_b + i * 128, bout + i * 128, 1, 128, 1 };
        tab.e[ne++] = { t_f_b1  + i * 512, bf1  + i * 512, 1, 512, 1 };
        tab.e[ne++] = { t_f_b2  + i * 128, bf2  + i * 128, 1, 128, 1 };
        tab.e[ne++] = { ln1g + i * 128, l1g + i * 128, 1, 128, 1 };
        tab.e[ne++] = { ln1b + i * 128, l1b + i * 128, 1, 128, 1 };
        tab.e[ne++] = { ln2g + i * 128, l2g + i * 128, 1, 128, 1 };
        tab.e[ne++] = { ln2b + i * 128, l2b + i * 128, 1, 128, 1 };
    }
    for (int i = 0; i < 2; i++) {
        tab.e[ne++] = { gw + (size_t)i * 128 * 256, wg + (size_t)i * 128 * 256, 128, 256, 0 };
        tab.e[ne++] = { gb   + i * 128, bg  + i * 128, 1, 128, 1 };
        tab.e[ne++] = { glng + i * 128, gg  + i * 128, 1, 128, 1 };
        tab.e[ne++] = { glnb + i * 128, gbv + i * 128, 1, 128, 1 };
    }

    // launches 1-5 (so launch 6 = trans1 qkv GEMM gets the ncu capture)
    param_conv<<<dim3(64, ne), 256>>>(tab, ne);                       // 1
    conv_x<<<(NN * 128 + 255) / 256, 256>>>(x, phx);                  // 2
    zero_kernel<<<(n + 255) / 256, 256>>>(pdeg, pcnt, n);             // 3
    hist_kernel<<<EG, 256>>>(esrc, pdeg, e);                          // 4
    scan1_kernel<<<SCAN_BLOCKS, 256>>>(pdeg, poff, pbsum, n);         // 5

    // ---- transformer layer ----
    auto run_trans = [&](const float* hin, float* hout, int i, bool final_layer) {
        gemm_tc<128, 384, false, false, false, false, 1><<<dim3(GX, 3), 256, SMEMSZ>>>(
            hin, nullptr, wqkv + (size_t)i * 384 * 128, bqkv + i * 384,
            nullptr, nullptr, nullptr, pqkv, n);
        attn_kernel<<<WARP_GRID, 256>>>(pqkv, samples, pattn, n);
        gemm_tc<128, 128, false, true, true, false, 1><<<dim3(GX, 1), 256, SMEMSZ>>>(
            pattn, nullptr, wout + (size_t)i * 128 * 128, bout + i * 128,
            hin, l1g + i * 128, l1b + i * 128, pa, n);
        gemm_tc<128, 512, true, false, false, false, 1><<<dim3(GX, 4), 256, SMEMSZ>>>(
            pa, nullptr, wf1 + (size_t)i * 512 * 128, bf1 + i * 512,
            nullptr, nullptr, nullptr, ptmp, n);
        if (final_layer) {
            gemm_tc<512, 128, false, true, true, false, 2><<<dim3(GX, 1), 256, SMEMSZ>>>(
                ptmp, nullptr, wf2 + (size_t)i * 128 * 512, bf2 + i * 128,
                pa, l2g + i * 128, l2b + i * 128, hout, n);
        } else {
            gemm_tc<512, 128, false, true, true, false, 1><<<dim3(GX, 1), 256, SMEMSZ>>>(
                ptmp, nullptr, wf2 + (size_t)i * 128 * 512, bf2 + i * 128,
                pa, l2g + i * 128, l2b + i * 128, hout, n);
        }
    };

    // ---- GNN layer ----
    auto run_gnn = [&](const float* hin, float* hout, int i) {
        agg_kernel<<<WARP_GRID, 256>>>(hin, poff, pcsr, pneigh, n);
        gemm_tc<256, 128, true, true, true, true, 1><<<dim3(GX, 1), 256, SMEMSZ>>>(
            hin, pneigh, wg + (size_t)i * 128 * 256, bg + i * 128,
            hin, gg + i * 128, gbv + i * 128, hout, n);
    };

    // trans1: qkv GEMM is launch #6 (profiled)
    gemm_tc<128, 384, false, false, false, false, 1><<<dim3(GX, 3), 256, SMEMSZ>>>(
        phx, nullptr, wqkv, bqkv, nullptr, nullptr, nullptr, pqkv, n);   // 6
    // finish CSR build (needed only before gnn1 agg)
    scan2_kernel<<<SCAN_BLOCKS, 256>>>(pbsum, poff, n);                  // 7
    scatter_kernel<<<EG, 256>>>(esrc, edst, poff, pcnt, pcsr, e);        // 8
    // rest of trans1
    attn_kernel<<<WARP_GRID, 256>>>(pqkv, samples, pattn, n);
    gemm_tc<128, 128, false, true, true, false, 1><<<dim3(GX, 1), 256, SMEMSZ>>>(
        pattn, nullptr, wout, bout, phx, l1g, l1b, pa, n);
    gemm_tc<128, 512, true, false, false, false, 1><<<dim3(GX, 4), 256, SMEMSZ>>>(
        pa, nullptr, wf1, bf1, nullptr, nullptr, nullptr, ptmp, n);
    gemm_tc<512, 128, false, true, true, false, 1><<<dim3(GX, 1), 256, SMEMSZ>>>(
        ptmp, nullptr, wf2, bf2, pa, l2g, l2b, ph, n);

    run_gnn(ph, ph2, 0);
    run_trans(ph2, ph, 1, false);
    run_gnn(ph, ph2, 1);
    run_trans(ph2, (float*)d_out, 2, true);
}

// round 5
// speedup vs baseline: 1.9678x; 1.0098x over previous
#include <cuda_runtime.h>

#define NN 50000
#define DD 128
#define EE 1600000
#define KATT 20
#define SCAN_TILE 4096
#define SCAN_BLOCKS ((NN + SCAN_TILE - 1) / SCAN_TILE)

// ---------------- scratch (static device allocations) ----------------
__device__ float g_qkv[NN * 384];
__device__ float g_attn[NN * DD];
__device__ float g_a[NN * DD];
__device__ float g_tmp[NN * 512];
__device__ float g_h[NN * DD];
__device__ float g_h2[NN * DD];
__device__ float g_neigh[NN * DD];
__device__ float g_hx[NN * DD];
__device__ int   g_deg[NN];
__device__ int   g_off[NN + 1];
__device__ int   g_cnt[NN];
__device__ int   g_csr[EE];
__device__ int   g_bsum[SCAN_BLOCKS];

// converted (tf32-rounded, permuted) parameters
__device__ float g_wqkv[3 * 384 * 128];
__device__ float g_wout[3 * 128 * 128];
__device__ float g_wf1 [3 * 512 * 128];
__device__ float g_wf2 [3 * 128 * 512];
__device__ float g_wg  [2 * 128 * 256];
__device__ float g_bqkv[3 * 384];
__device__ float g_bout[3 * 128];
__device__ float g_bf1 [3 * 512];
__device__ float g_bf2 [3 * 128];
__device__ float g_l1g [3 * 128];
__device__ float g_l1b [3 * 128];
__device__ float g_l2g [3 * 128];
__device__ float g_l2b [3 * 128];
__device__ float g_bg  [2 * 128];
__device__ float g_gg  [2 * 128];
__device__ float g_gb  [2 * 128];

// ---------------- helpers ----------------
__device__ __forceinline__ unsigned tf32cvt(float x) {
    unsigned r;
    asm("cvt.rna.tf32.f32 %0, %1;" : "=r"(r) : "f"(x));
    return r;
}
__device__ __forceinline__ float tf32r(float x) { return __uint_as_float(tf32cvt(x)); }

// within-8 column permutation for mma k-fragments (logical -> physical)
__device__ __forceinline__ int gperm(int i) {
    return (i & ~7) + ((i & 3) << 1) + ((i & 4) >> 2);
}

__device__ __forceinline__ void mma_tf32(float c[4], const unsigned a[4],
                                         unsigned b0, unsigned b1) {
    asm("mma.sync.aligned.m16n8k8.row.col.f32.tf32.tf32.f32 "
        "{%0,%1,%2,%3}, {%4,%5,%6,%7}, {%8,%9}, {%0,%1,%2,%3};\n"
        : "+f"(c[0]), "+f"(c[1]), "+f"(c[2]), "+f"(c[3])
        : "r"(a[0]), "r"(a[1]), "r"(a[2]), "r"(a[3]), "r"(b0), "r"(b1));
}

__device__ __forceinline__ void cp16(void* sdst, const void* gsrc, int sz) {
    unsigned s = (unsigned)__cvta_generic_to_shared(sdst);
    asm volatile("cp.async.cg.shared.global [%0], [%1], 16, %2;\n"
                 :: "r"(s), "l"(gsrc), "r"(sz));
}
__device__ __forceinline__ void cp_commit() {
    asm volatile("cp.async.commit_group;\n");
}
__device__ __forceinline__ void cp_wait1() {
    asm volatile("cp.async.wait_group 1;\n");
}
__device__ __forceinline__ void cp_wait0() {
    asm volatile("cp.async.wait_group 0;\n");
}

// ---------------- parameter conversion ----------------
struct PEnt { const float* s; float* d; int rows; int cols; int mode; };
struct PTab { PEnt e[48]; };

__global__ void param_conv(PTab t, int n) {
    const int ei = blockIdx.y;
    if (ei >= n) return;
    const PEnt en = t.e[ei];
    const int total = en.rows * en.cols;
    for (int i = blockIdx.x * blockDim.x + threadIdx.x; i < total;
         i += gridDim.x * blockDim.x) {
        if (en.mode == 0) {           // matrix: permute both dims + tf32 round
            const int r = i / en.cols, c = i % en.cols;
            en.d[(size_t)gperm(r) * en.cols + gperm(c)] = tf32r(en.s[i]);
        } else {                      // vector: permute only
            en.d[gperm(i)] = en.s[i];
        }
    }
}

__global__ void conv_x(const float* __restrict__ x, float* __restrict__ o) {
    const int i = blockIdx.x * blockDim.x + threadIdx.x;
    if (i < NN * 128) {
        const int r = i >> 7, c = i & 127;
        o[(r << 7) + gperm(c)] = tf32r(x[i]);
    }
}

// ---------------- fused TF32 tensor-core GEMM (cp.async pipelined) ----------------
// All operands live in "permuted world" (within-8 col permutation) and are
// pre-rounded to tf32, so smem tiles are raw byte copies of gmem.
// Block 128x128, 8 warps (4m x 2n), warp tile 32x64, BK=32, 2-stage cp.async.
// OMODE: 1 = store tf32-rounded (activation), 2 = final store (inverse-permute cols).
template <int IN, int OUT, bool RELU, bool RES, bool LN, bool SPLIT, int OMODE>
__global__ __launch_bounds__(256, 2) void gemm_tc(
    const float* __restrict__ A, const float* __restrict__ A2,
    const float* __restrict__ W, const float* __restrict__ bias,
    const float* __restrict__ res,
    const float* __restrict__ lng, const float* __restrict__ lnb,
    float* __restrict__ C, int nrows)
{
    constexpr int SST = 40;                      // smem row stride (floats)
    extern __shared__ float smem[];
    float* Asm[2] = { smem,             smem + 128 * SST };
    float* Wsm[2] = { smem + 2 * 128 * SST, smem + 3 * 128 * SST };
    float2* lnp   = (float2*)(smem + 4 * 128 * SST);   // [2][128]

    const int tid    = threadIdx.x;
    const int lane   = tid & 31;
    const int warp   = tid >> 5;
    const int warp_m = warp & 3;
    const int warp_n = warp >> 2;
    const int g      = lane >> 2;
    const int t      = lane & 3;
    const int row0   = blockIdx.x * 128;
    const int col0   = blockIdx.y * 128;
    const int colb   = warp_n * 64;

    float acc[2][8][4];
#pragma unroll
    for (int fm = 0; fm < 2; fm++)
#pragma unroll
        for (int nf = 0; nf < 8; nf++)
#pragma unroll
            for (int r = 0; r < 4; r++) acc[fm][nf][r] = 0.f;

    constexpr int NCH = IN / 32;

    auto issue = [&](int chunk, int st) {
        const int kc = chunk * 32;
        float* as = Asm[st];
        float* ws = Wsm[st];
#pragma unroll
        for (int it = 0; it < 4; it++) {
            const int idx = it * 256 + tid;
            const int r   = idx >> 3;        // 0..127
            const int c   = idx & 7;         // 16B chunk within 32 floats
            const int kk  = kc + c * 4;
            const int grow = row0 + r;
            const bool ok  = (grow < nrows);
            const int crow = ok ? grow : 0;
            const float* ap;
            if (SPLIT) {
                ap = (kk < 128) ? &A[(size_t)crow * 128 + kk]
                                : &A2[(size_t)crow * 128 + (kk - 128)];
            } else {
                ap = &A[(size_t)crow * IN + kk];
            }
            cp16(as + r * SST + c * 4, ap, ok ? 16 : 0);
            cp16(ws + r * SST + c * 4, &W[(size_t)(col0 + r) * IN + kk], 16);
        }
        cp_commit();
    };

    auto compute = [&](int st) {
        const float* as = Asm[st];
        const float* ws = Wsm[st];
#pragma unroll
        for (int ks = 0; ks < 4; ks++) {
            const int kp = ks * 8 + 2 * t;
            unsigned a[2][4];
#pragma unroll
            for (int fm = 0; fm < 2; fm++) {
                const int rb = warp_m * 32 + fm * 16;
                const uint2 p0 = *(const uint2*)(as + (rb + g) * SST + kp);
                const uint2 p1 = *(const uint2*)(as + (rb + g + 8) * SST + kp);
                a[fm][0] = p0.x; a[fm][1] = p1.x;
                a[fm][2] = p0.y; a[fm][3] = p1.y;
            }
#pragma unroll
            for (int nf = 0; nf < 8; nf++) {
                const uint2 bb = *(const uint2*)(ws + (colb + nf * 8 + g) * SST + kp);
                mma_tf32(acc[0][nf], a[0], bb.x, bb.y);
                mma_tf32(acc[1][nf], a[1], bb.x, bb.y);
            }
        }
    };

    issue(0, 0);
#pragma unroll 1
    for (int ch = 0; ch < NCH; ch++) {
        if (ch + 1 < NCH) {
            issue(ch + 1, (ch + 1) & 1);
            cp_wait1();
        } else {
            cp_wait0();
        }
        __syncthreads();
        compute(ch & 1);
        __syncthreads();
    }

    // ---------------- epilogue ----------------
    float2 bias2[8];
#pragma unroll
    for (int nf = 0; nf < 8; nf++)
        bias2[nf] = *(const float2*)&bias[col0 + colb + nf * 8 + 2 * t];

#pragma unroll
    for (int fm = 0; fm < 2; fm++) {
#pragma unroll
        for (int ro = 0; ro < 2; ro++) {
            const int row  = warp_m * 32 + fm * 16 + ro * 8 + g;
            const int grow = row0 + row;
            const bool ok  = (grow < nrows);
            float s = 0.f, s2 = 0.f;
#pragma unroll
            for (int nf = 0; nf < 8; nf++) {
                float v0 = acc[fm][nf][ro * 2 + 0] + bias2[nf].x;
                float v1 = acc[fm][nf][ro * 2 + 1] + bias2[nf].y;
                if (RELU) { v0 = fmaxf(v0, 0.f); v1 = fmaxf(v1, 0.f); }
                if (RES && ok) {
                    const float2 rv = *(const float2*)
                        &res[(size_t)grow * OUT + col0 + colb + nf * 8 + 2 * t];
                    v0 += rv.x; v1 += rv.y;
                }
                acc[fm][nf][ro * 2 + 0] = v0;
                acc[fm][nf][ro * 2 + 1] = v1;
                if (LN) { s += v0 + v1; s2 += v0 * v0 + v1 * v1; }
            }
            if (LN) {
                s  += __shfl_xor_sync(0xffffffffu, s, 1);
                s2 += __shfl_xor_sync(0xffffffffu, s2, 1);
                s  += __shfl_xor_sync(0xffffffffu, s, 2);
                s2 += __shfl_xor_sync(0xffffffffu, s2, 2);
                if (t == 0) lnp[warp_n * 128 + row] = make_float2(s, s2);
            }
        }
    }
    if (LN) __syncthreads();

#pragma unroll
    for (int fm = 0; fm < 2; fm++) {
#pragma unroll
        for (int ro = 0; ro < 2; ro++) {
            const int row  = warp_m * 32 + fm * 16 + ro * 8 + g;
            const int grow = row0 + row;
            if (grow >= nrows) continue;
            float mean = 0.f, rstd = 1.f;
            if (LN) {
                const float2 p0 = lnp[row];
                const float2 p1 = lnp[128 + row];
                const float s  = p0.x + p1.x;
                const float s2 = p0.y + p1.y;
                mean = s * (1.f / 128.f);
                const float var = s2 * (1.f / 128.f) - mean * mean;
                rstd = rsqrtf(var + 1e-5f);
            }
#pragma unroll
            for (int nf = 0; nf < 8; nf++) {
                const int col = col0 + colb + nf * 8 + 2 * t;
                float v0 = acc[fm][nf][ro * 2 + 0];
                float v1 = acc[fm][nf][ro * 2 + 1];
                if (LN) {
                    const float2 gv = *(const float2*)&lng[col];
                    const float2 bb = *(const float2*)&lnb[col];
                    v0 = (v0 - mean) * rstd * gv.x + bb.x;
                    v1 = (v1 - mean) * rstd * gv.y + bb.y;
                }
                if (OMODE == 1) {
                    *(float2*)&C[(size_t)grow * OUT + col] =
                        make_float2(tf32r(v0), tf32r(v1));
                } else {
                    const int l0 = (col & ~7) + ((col & 1) << 2) + ((col & 7) >> 1);
                    const int c1 = col + 1;
                    const int l1 = (c1 & ~7) + ((c1 & 1) << 2) + ((c1 & 7) >> 1);
                    C[(size_t)grow * OUT + l0] = v0;
                    C[(size_t)grow * OUT + l1] = v1;
                }
            }
        }
    }
}

// ---------------- attention: warp per node (permuted world) ----------------
__global__ __launch_bounds__(256) void attn_kernel(
    const float* __restrict__ qkv, const int* __restrict__ samp,
    float* __restrict__ out, int n)
{
    const int warp = (blockIdx.x * blockDim.x + threadIdx.x) >> 5;
    const int lane = threadIdx.x & 31;
    if (warp >= n) return;
    const int node = warp;
    const int c0 = lane * 4;

    const float4 q = *(const float4*)&qkv[node * 384 + c0];
    int idxs[KATT];
#pragma unroll
    for (int j = 0; j < KATT; j++) idxs[j] = __ldg(&samp[node * KATT + j]);

    const float scale = 0.17677669529663687f;   // 1/sqrt(32)
    float s[KATT];
    float mx = -1e30f;
#pragma unroll
    for (int j = 0; j < KATT; j++) {
        const float4 kv = *(const float4*)&qkv[idxs[j] * 384 + 128 + c0];
        float d = q.x * kv.x + q.y * kv.y + q.z * kv.z + q.w * kv.w;
        d += __shfl_xor_sync(0xffffffffu, d, 1);
        d += __shfl_xor_sync(0xffffffffu, d, 2);
        d += __shfl_xor_sync(0xffffffffu, d, 4);
        s[j] = d * scale;
        mx = fmaxf(mx, s[j]);
    }
    float sum = 0.f;
#pragma unroll
    for (int j = 0; j < KATT; j++) { s[j] = __expf(s[j] - mx); sum += s[j]; }
    const float inv = 1.f / sum;

    float4 a = make_float4(0.f, 0.f, 0.f, 0.f);
#pragma unroll
    for (int j = 0; j < KATT; j++) {
        const float4 vv = *(const float4*)&qkv[idxs[j] * 384 + 256 + c0];
        const float w = s[j] * inv;
        a.x += w * vv.x; a.y += w * vv.y;
        a.z += w * vv.z; a.w += w * vv.w;
    }
    *(float4*)&out[node * 128 + c0] =
        make_float4(tf32r(a.x), tf32r(a.y), tf32r(a.z), tf32r(a.w));
}

// ---------------- GNN CSR build + aggregate ----------------
__global__ void zero_kernel(int* __restrict__ a, int* __restrict__ b, int n) {
    const int i = blockIdx.x * blockDim.x + threadIdx.x;
    if (i < n) { a[i] = 0; b[i] = 0; }
}

__global__ void hist_kernel(const int* __restrict__ src, int* __restrict__ deg, int e) {
    const int i = blockIdx.x * blockDim.x + threadIdx.x;
    if (i < e) atomicAdd(&deg[src[i]], 1);
}

// scan stage 1: per-block exclusive scan (tile = 4096), write block totals
__global__ __launch_bounds__(256) void scan1_kernel(
    const int* __restrict__ deg, int* __restrict__ off, int* __restrict__ bsum, int n)
{
    __shared__ int wsum[8];
    const int tid  = threadIdx.x;
    const int lane = tid & 31, wid = tid >> 5;
    const int base = blockIdx.x * SCAN_TILE + tid * 16;

    int v[16];
    int tsum = 0;
#pragma unroll
    for (int i = 0; i < 16; i++) {
        const int gi = base + i;
        v[i] = (gi < n) ? deg[gi] : 0;
        tsum += v[i];
    }
    int x = tsum;
#pragma unroll
    for (int d = 1; d < 32; d <<= 1) {
        const int t = __shfl_up_sync(0xffffffffu, x, d);
        if (lane >= d) x += t;
    }
    if (lane == 31) wsum[wid] = x;
    __syncthreads();
    int wpre = 0;
#pragma unroll
    for (int w = 0; w < 8; w++) wpre += (w < wid) ? wsum[w] : 0;
    int run = wpre + x - tsum;
#pragma unroll
    for (int i = 0; i < 16; i++) {
        const int gi = base + i;
        if (gi < n) off[gi] = run;
        run += v[i];
    }
    if (tid == 255) bsum[blockIdx.x] = wpre + x;
}

// scan stage 2: add cross-block prefix (redundant tiny reduction per block)
__global__ __launch_bounds__(256) void scan2_kernel(
    const int* __restrict__ bsum, int* __restrict__ off, int n)
{
    __shared__ int pre_s, tot_s;
    if (threadIdx.x == 0) {
        int p = 0, t = 0;
#pragma unroll
        for (int b = 0; b < SCAN_BLOCKS; b++) {
            if (b < (int)blockIdx.x) p += bsum[b];
            t += bsum[b];
        }
        pre_s = p; tot_s = t;
    }
    __syncthreads();
    const int pre = pre_s;
    const int base = blockIdx.x * SCAN_TILE + threadIdx.x * 16;
#pragma unroll
    for (int i = 0; i < 16; i++) {
        const int gi = base + i;
        if (gi < n) off[gi] += pre;
    }
    if (blockIdx.x == 0 && threadIdx.x == 0) off[n] = tot_s;
}

__global__ void scatter_kernel(const int* __restrict__ src, const int* __restrict__ dst,
                               const int* __restrict__ off, int* __restrict__ cnt,
                               int* __restrict__ csr, int e) {
    const int i = blockIdx.x * blockDim.x + threadIdx.x;
    if (i < e) {
        const int s = src[i];
        const int pos = off[s] + atomicAdd(&cnt[s], 1);
        csr[pos] = dst[i];
    }
}

__global__ __launch_bounds__(256) void agg_kernel(
    const float* __restrict__ h, const int* __restrict__ off,
    const int* __restrict__ csr, float* __restrict__ neigh, int n)
{
    const int warp = (blockIdx.x * blockDim.x + threadIdx.x) >> 5;
    const int lane = threadIdx.x & 31;
    if (warp >= n) return;
    const int beg = off[warp], end = off[warp + 1];
    float4 acc0 = make_float4(0.f, 0.f, 0.f, 0.f);
    float4 acc1 = make_float4(0.f, 0.f, 0.f, 0.f);
    float4 acc2 = make_float4(0.f, 0.f, 0.f, 0.f);
    float4 acc3 = make_float4(0.f, 0.f, 0.f, 0.f);
    int e = beg;
    for (; e + 4 <= end; e += 4) {
        const int d0 = csr[e];
        const int d1 = csr[e + 1];
        const int d2 = csr[e + 2];
        const int d3 = csr[e + 3];
        const float4 h0 = *(const float4*)&h[(size_t)d0 * 128 + lane * 4];
        const float4 h1 = *(const float4*)&h[(size_t)d1 * 128 + lane * 4];
        const float4 h2 = *(const float4*)&h[(size_t)d2 * 128 + lane * 4];
        const float4 h3 = *(const float4*)&h[(size_t)d3 * 128 + lane * 4];
        acc0.x += h0.x; acc0.y += h0.y; acc0.z += h0.z; acc0.w += h0.w;
        acc1.x += h1.x; acc1.y += h1.y; acc1.z += h1.z; acc1.w += h1.w;
        acc2.x += h2.x; acc2.y += h2.y; acc2.z += h2.z; acc2.w += h2.w;
        acc3.x += h3.x; acc3.y += h3.y; acc3.z += h3.z; acc3.w += h3.w;
    }
    for (; e < end; e++) {
        const int d0 = csr[e];
        const float4 h0 = *(const float4*)&h[(size_t)d0 * 128 + lane * 4];
        acc0.x += h0.x; acc0.y += h0.y; acc0.z += h0.z; acc0.w += h0.w;
    }
    acc0.x += acc1.x; acc0.y += acc1.y; acc0.z += acc1.z; acc0.w += acc1.w;
    acc2.x += acc3.x; acc2.y += acc3.y; acc2.z += acc3.z; acc2.w += acc3.w;
    acc0.x += acc2.x; acc0.y += acc2.y; acc0.z += acc2.z; acc0.w += acc2.w;
    *(float4*)&neigh[(size_t)warp * 128 + lane * 4] =
        make_float4(tf32r(acc0.x), tf32r(acc0.y), tf32r(acc0.z), tf32r(acc0.w));
}

// ---------------- host orchestration ----------------
extern "C" void kernel_launch(void* const* d_in, const int* in_sizes, int n_in,
                              void* d_out, int out_size)
{
    const float* x       = (const float*)d_in[0];
    const int*   samples = (const int*)d_in[1];
    const int*   esrc    = (const int*)d_in[2];
    const int*   edst    = (const int*)d_in[3];
    const float* t_in_w  = (const float*)d_in[4];
    const float* t_in_b  = (const float*)d_in[5];
    const float* t_out_w = (const float*)d_in[6];
    const float* t_out_b = (const float*)d_in[7];
    const float* t_f_w1  = (const float*)d_in[8];
    const float* t_f_b1  = (const float*)d_in[9];
    const float* t_f_w2  = (const float*)d_in[10];
    const float* t_f_b2  = (const float*)d_in[11];
    const float* ln1g    = (const float*)d_in[12];
    const float* ln1b    = (const float*)d_in[13];
    const float* ln2g    = (const float*)d_in[14];
    const float* ln2b    = (const float*)d_in[15];
    const float* gw      = (const float*)d_in[16];
    const float* gb      = (const float*)d_in[17];
    const float* glng    = (const float*)d_in[18];
    const float* glnb    = (const float*)d_in[19];

    float *pqkv, *pattn, *pa, *ptmp, *ph, *ph2, *pneigh, *phx;
    int *pdeg, *poff, *pcnt, *pcsr, *pbsum;
    float *wqkv, *wout, *wf1, *wf2, *wg;
    float *bqkv, *bout, *bf1, *bf2, *l1g, *l1b, *l2g, *l2b, *bg, *gg, *gbv;
    cudaGetSymbolAddress((void**)&pqkv,   g_qkv);
    cudaGetSymbolAddress((void**)&pattn,  g_attn);
    cudaGetSymbolAddress((void**)&pa,     g_a);
    cudaGetSymbolAddress((void**)&ptmp,   g_tmp);
    cudaGetSymbolAddress((void**)&ph,     g_h);
    cudaGetSymbolAddress((void**)&ph2,    g_h2);
    cudaGetSymbolAddress((void**)&pneigh, g_neigh);
    cudaGetSymbolAddress((void**)&phx,    g_hx);
    cudaGetSymbolAddress((void**)&pdeg,   g_deg);
    cudaGetSymbolAddress((void**)&poff,   g_off);
    cudaGetSymbolAddress((void**)&pcnt,   g_cnt);
    cudaGetSymbolAddress((void**)&pcsr,   g_csr);
    cudaGetSymbolAddress((void**)&pbsum,  g_bsum);
    cudaGetSymbolAddress((void**)&wqkv,   g_wqkv);
    cudaGetSymbolAddress((void**)&wout,   g_wout);
    cudaGetSymbolAddress((void**)&wf1,    g_wf1);
    cudaGetSymbolAddress((void**)&wf2,    g_wf2);
    cudaGetSymbolAddress((void**)&wg,     g_wg);
    cudaGetSymbolAddress((void**)&bqkv,   g_bqkv);
    cudaGetSymbolAddress((void**)&bout,   g_bout);
    cudaGetSymbolAddress((void**)&bf1,    g_bf1);
    cudaGetSymbolAddress((void**)&bf2,    g_bf2);
    cudaGetSymbolAddress((void**)&l1g,    g_l1g);
    cudaGetSymbolAddress((void**)&l1b,    g_l1b);
    cudaGetSymbolAddress((void**)&l2g,    g_l2g);
    cudaGetSymbolAddress((void**)&l2b,    g_l2b);
    cudaGetSymbolAddress((void**)&bg,     g_bg);
    cudaGetSymbolAddress((void**)&gg,     g_gg);
    cudaGetSymbolAddress((void**)&gbv,    g_gb);

    const int n = NN;
    const int e = EE;
    const int GX = (n + 127) / 128;
    const int WARP_GRID = (n + 7) / 8;
    const int EG = (e + 255) / 256;
    const size_t SMEMSZ = (4 * 128 * 40) * sizeof(float) + 256 * sizeof(float2);

    cudaFuncSetAttribute(gemm_tc<128, 384, false, false, false, false, 1>,
                         cudaFuncAttributeMaxDynamicSharedMemorySize, (int)SMEMSZ);
    cudaFuncSetAttribute(gemm_tc<128, 128, false, true, true, false, 1>,
                         cudaFuncAttributeMaxDynamicSharedMemorySize, (int)SMEMSZ);
    cudaFuncSetAttribute(gemm_tc<128, 512, true, false, false, false, 1>,
                         cudaFuncAttributeMaxDynamicSharedMemorySize, (int)SMEMSZ);
    cudaFuncSetAttribute(gemm_tc<512, 128, false, true, true, false, 1>,
                         cudaFuncAttributeMaxDynamicSharedMemorySize, (int)SMEMSZ);
    cudaFuncSetAttribute(gemm_tc<512, 128, false, true, true, false, 2>,
                         cudaFuncAttributeMaxDynamicSharedMemorySize, (int)SMEMSZ);
    cudaFuncSetAttribute(gemm_tc<256, 128, true, true, true, true, 1>,
                         cudaFuncAttributeMaxDynamicSharedMemorySize, (int)SMEMSZ);

    // side stream + events (created once; graph fork/join pattern)
    static cudaStream_t sB = nullptr;
    static cudaEvent_t evFork = nullptr, evJoin = nullptr;
    if (sB == nullptr) {
        cudaStreamCreateWithFlags(&sB, cudaStreamNonBlocking);
        cudaEventCreateWithFlags(&evFork, cudaEventDisableTiming);
        cudaEventCreateWithFlags(&evJoin, cudaEventDisableTiming);
    }

    // ---- parameter conversion table ----
    PTab tab;
    int ne = 0;
    for (int i = 0; i < 3; i++) {
        tab.e[ne++] = { t_in_w  + (size_t)i * 384 * 128, wqkv + (size_t)i * 384 * 128, 384, 128, 0 };
        tab.e[ne++] = { t_out_w + (size_t)i * 128 * 128, wout + (size_t)i * 128 * 128, 128, 128, 0 };
        tab.e[ne++] = { t_f_w1  + (size_t)i * 512 * 128, wf1  + (size_t)i * 512 * 128, 512, 128, 0 };
        tab.e[ne++] = { t_f_w2  + (size_t)i * 128 * 512, wf2  + (size_t)i * 128 * 512, 128, 512, 0 };
        tab.e[ne++] = { t_in_b  + i * 384, bqkv + i * 384, 1, 384, 1 };
        tab.e[ne++] = { t_out_b + i * 128, bout + i * 128, 1, 128, 1 };
        tab.e[ne++] = { t_f_b1  + i * 512, bf1  + i * 512, 1, 512, 1 };
        tab.e[ne++] = { t_f_b2  + i * 128, bf2  + i * 128, 1, 128, 1 };
        tab.e[ne++] = { ln1g + i * 128, l1g + i * 128, 1, 128, 1 };
        tab.e[ne++] = { ln1b + i * 128, l1b + i * 128, 1, 128, 1 };
        tab.e[ne++] = { ln2g + i * 128, l2g + i * 128, 1, 128, 1 };
        tab.e[ne++] = { ln2b + i * 128, l2b + i * 128, 1, 128, 1 };
    }
    for (int i = 0; i < 2; i++) {
        tab.e[ne++] = { gw + (size_t)i * 128 * 256, wg + (size_t)i * 128 * 256, 128, 256, 0 };
        tab.e[ne++] = { gb   + i * 128, bg  + i * 128, 1, 128, 1 };
        tab.e[ne++] = { glng + i * 128, gg  + i * 128, 1, 128, 1 };
        tab.e[ne++] = { glnb + i * 128, gbv + i * 128, 1, 128, 1 };
    }

    // fork point: CSR build depends only on inputs
    cudaEventRecord(evFork, 0);
    cudaStreamWaitEvent(sB, evFork, 0);

    // ---- main stream: conversions + trans1 ----
    param_conv<<<dim3(64, ne), 256>>>(tab, ne);
    conv_x<<<(NN * 128 + 255) / 256, 256>>>(x, phx);

    gemm_tc<128, 384, false, false, false, false, 1><<<dim3(GX, 3), 256, SMEMSZ>>>(
        phx, nullptr, wqkv, bqkv, nullptr, nullptr, nullptr, pqkv, n);
    attn_kernel<<<WARP_GRID, 256>>>(pqkv, samples, pattn, n);
    gemm_tc<128, 128, false, true, true, false, 1><<<dim3(GX, 1), 256, SMEMSZ>>>(
        pattn, nullptr, wout, bout, phx, l1g, l1b, pa, n);
    gemm_tc<128, 512, true, false, false, false, 1><<<dim3(GX, 4), 256, SMEMSZ>>>(
        pa, nullptr, wf1, bf1, nullptr, nullptr, nullptr, ptmp, n);
    gemm_tc<512, 128, false, true, true, false, 1><<<dim3(GX, 1), 256, SMEMSZ>>>(
        ptmp, nullptr, wf2, bf2, pa, l2g, l2b, ph, n);

    // ---- side stream: CSR build (overlaps trans1) ----
    zero_kernel<<<(n + 255) / 256, 256, 0, sB>>>(pdeg, pcnt, n);
    hist_kernel<<<EG, 256, 0, sB>>>(esrc, pdeg, e);
    scan1_kernel<<<SCAN_BLOCKS, 256, 0, sB>>>(pdeg, poff, pbsum, n);
    scan2_kernel<<<SCAN_BLOCKS, 256, 0, sB>>>(pbsum, poff, n);
    scatter_kernel<<<EG, 256, 0, sB>>>(esrc, edst, poff, pcnt, pcsr, e);
    cudaEventRecord(evJoin, sB);

    // join before first aggregation
    cudaStreamWaitEvent(0, evJoin, 0);

    // ---- remaining layers (main stream) ----
    auto run_trans = [&](const float* hin, float* hout, int i, bool final_layer) {
        gemm_tc<128, 384, false, false, false, false, 1><<<dim3(GX, 3), 256, SMEMSZ>>>(
            hin, nullptr, wqkv + (size_t)i * 384 * 128, bqkv + i * 384,
            nullptr, nullptr, nullptr, pqkv, n);
        attn_kernel<<<WARP_GRID, 256>>>(pqkv, samples, pattn, n);
        gemm_tc<128, 128, false, true, true, false, 1><<<dim3(GX, 1), 256, SMEMSZ>>>(
            pattn, nullptr, wout + (size_t)i * 128 * 128, bout + i * 128,
            hin, l1g + i * 128, l1b + i * 128, pa, n);
        gemm_tc<128, 512, true, false, false, false, 1><<<dim3(GX, 4), 256, SMEMSZ>>>(
            pa, nullptr, wf1 + (size_t)i * 512 * 128, bf1 + i * 512,
            nullptr, nullptr, nullptr, ptmp, n);
        if (final_layer) {
            gemm_tc<512, 128, false, true, true, false, 2><<<dim3(GX, 1), 256, SMEMSZ>>>(
                ptmp, nullptr, wf2 + (size_t)i * 128 * 512, bf2 + i * 128,
                pa, l2g + i * 128, l2b + i * 128, hout, n);
        } else {
            gemm_tc<512, 128, false, true, true, false, 1><<<dim3(GX, 1), 256, SMEMSZ>>>(
                ptmp, nullptr, wf2 + (size_t)i * 128 * 512, bf2 + i * 128,
                pa, l2g + i * 128, l2b + i * 128, hout, n);
        }
    };

    auto run_gnn = [&](const float* hin, float* hout, int i) {
        agg_kernel<<<WARP_GRID, 256>>>(hin, poff, pcsr, pneigh, n);
        gemm_tc<256, 128, true, true, true, true, 1><<<dim3(GX, 1), 256, SMEMSZ>>>(
            hin, pneigh, wg + (size_t)i * 128 * 256, bg + i * 128,
            hin, gg + i * 128, gbv + i * 128, hout, n);
    };

    run_gnn(ph, ph2, 0);
    run_trans(ph2, ph, 1, false);
    run_gnn(ph, ph2, 1);
    run_trans(ph2, (float*)d_out, 2, true);
}